// round 14
// baseline (speedup 1.0000x reference)
#include <cuda_runtime.h>
#include <cuda_bf16.h>
#include <math.h>
#include <stdint.h>

#define LAYERS 4
#define D 512
#define H 8
#define HD 64
#define FF 1024
#define B 64
#define S 64
#define M_TOT (B * S)
#define EPS 1e-5f

// ---------------------------------------------------------------------------
// Scratch buffers
// ---------------------------------------------------------------------------
__device__ float g_x[M_TOT * D];
__device__ float g_qkv[M_TOT * 3 * D];
__device__ float g_ao[M_TOT * D];
__device__ float g_tmp[M_TOT * D];
__device__ float g_h[M_TOT * FF];
__device__ float g_f[M_TOT * FF];
__device__ float g_t[M_TOT * FF];

__device__ int8_t q_x1[M_TOT * D],  q_x2[M_TOT * D];
__device__ int8_t q_ao1[M_TOT * D], q_ao2[M_TOT * D];
__device__ int8_t q_h1[M_TOT * FF], q_h2[M_TOT * FF];
__device__ int8_t q_wqkv1[LAYERS * 3 * D * D], q_wqkv2[LAYERS * 3 * D * D];
__device__ int8_t q_wo1[LAYERS * D * D],       q_wo2[LAYERS * D * D];
__device__ int8_t q_w11[LAYERS * FF * D],      q_w12[LAYERS * FF * D];
__device__ int8_t q_w21[LAYERS * D * FF],      q_w22[LAYERS * D * FF];
__device__ int8_t q_wm1f1[FF * D], q_wm1f2[FF * D];
__device__ int8_t q_wm1t1[FF * D], q_wm1t2[FF * D];

__device__ float s_x[M_TOT], s_ao[M_TOT], s_h[M_TOT];
__device__ float s_wqkv[LAYERS * 3 * D], s_wo[LAYERS * D];
__device__ float s_w1[LAYERS * FF], s_w2[LAYERS * D];
__device__ float s_wm1f[FF], s_wm1t[FF];

// ---------------------------------------------------------------------------
// Helpers
// ---------------------------------------------------------------------------
__device__ __forceinline__ float gelu_exact(float x) {
    return 0.5f * x * (1.0f + erff(x * 0.70710678118654752f));
}
__device__ __forceinline__ float tanh_fast(float x) {
    float y;
    asm("tanh.approx.f32 %0, %1;" : "=f"(y) : "f"(x));
    return y;
}
__device__ __forceinline__ float gelu_fast(float x) {
    float u = x * x;
    float z = x * fmaf(0.0356774081f, u, 0.7978845608f);
    float th = tanh_fast(z);
    float hx = 0.5f * x;
    return fmaf(hx, th, hx);
}
__device__ __forceinline__ uint32_t smem_u32(const void* p) {
    uint32_t a;
    asm("{ .reg .u64 t; cvta.to.shared.u64 t, %1; cvt.u32.u64 %0, t; }"
        : "=r"(a) : "l"(p));
    return a;
}
__device__ __forceinline__ void ldmx4(uint32_t* r, uint32_t addr) {
    asm volatile("ldmatrix.sync.aligned.m8n8.x4.shared.b16 {%0,%1,%2,%3}, [%4];"
                 : "=r"(r[0]), "=r"(r[1]), "=r"(r[2]), "=r"(r[3]) : "r"(addr));
}
__device__ __forceinline__ void imma(int* d, const uint32_t* a, const uint32_t* b) {
    asm volatile(
        "mma.sync.aligned.m16n8k32.row.col.s32.s8.s8.s32 "
        "{%0,%1,%2,%3}, {%4,%5,%6,%7}, {%8,%9}, {%0,%1,%2,%3};"
        : "+r"(d[0]), "+r"(d[1]), "+r"(d[2]), "+r"(d[3])
        : "r"(a[0]), "r"(a[1]), "r"(a[2]), "r"(a[3]), "r"(b[0]), "r"(b[1]));
}
__device__ __forceinline__ void cp16(uint32_t saddr, const void* gptr) {
    asm volatile("cp.async.cg.shared.global [%0], [%1], 16;"
                 :: "r"(saddr), "l"(gptr));
}
__device__ __forceinline__ void cp_commit() {
    asm volatile("cp.async.commit_group;");
}
template <int N>
__device__ __forceinline__ void cp_wait() {
    asm volatile("cp.async.wait_group %0;" :: "n"(N));
}

// ---------------------------------------------------------------------------
// Block-level (128 threads) two-level int8 row quantization
// ---------------------------------------------------------------------------
template <int LEN>
__device__ __forceinline__ void quant_row_block(
    const float* __restrict__ src, int8_t* __restrict__ q1row,
    int8_t* __restrict__ q2row, float* __restrict__ scale_slot,
    float* __restrict__ cpy)
{
    const int tid = threadIdx.x;
    const int warp = tid >> 5, lane = tid & 31;
    float4 v[LEN / 512];
    float m = 0.0f;
#pragma unroll
    for (int p = 0; p < LEN / 512; p++) {
        v[p] = *((const float4*)src + p * 128 + tid);
        m = fmaxf(m, fmaxf(fmaxf(fabsf(v[p].x), fabsf(v[p].y)),
                           fmaxf(fabsf(v[p].z), fabsf(v[p].w))));
    }
#pragma unroll
    for (int o = 16; o > 0; o >>= 1) m = fmaxf(m, __shfl_xor_sync(~0u, m, o));
    __shared__ float sm[4];
    if (lane == 0) sm[warp] = m;
    __syncthreads();
    m = fmaxf(fmaxf(sm[0], sm[1]), fmaxf(sm[2], sm[3]));
    m = fmaxf(m, 1e-30f);

    const float s1 = m * (1.0f / 127.0f);
    const float i1 = 127.0f / m;
    const float i2 = 254.0f / s1;
    if (tid == 0) *scale_slot = s1;

    int* q1p = (int*)q1row;
    int* q2p = (int*)q2row;
#pragma unroll
    for (int p = 0; p < LEN / 512; p++) {
        float xs[4] = {v[p].x, v[p].y, v[p].z, v[p].w};
        int pk1 = 0, pk2 = 0;
#pragma unroll
        for (int e = 0; e < 4; e++) {
            int a = __float2int_rn(xs[e] * i1);
            float r = xs[e] - s1 * (float)a;
            int b2 = __float2int_rn(r * i2);
            b2 = max(-127, min(127, b2));
            pk1 |= (a & 255) << (8 * e);
            pk2 |= (b2 & 255) << (8 * e);
        }
        q1p[p * 128 + tid] = pk1;
        q2p[p * 128 + tid] = pk2;
        if (cpy) *((float4*)cpy + p * 128 + tid) = v[p];
    }
}

template <int LEN>
__global__ void __launch_bounds__(128) quant_rows(
    const float* __restrict__ src, int lds,
    int8_t* __restrict__ q1, int8_t* __restrict__ q2,
    float* __restrict__ scale, float* __restrict__ cpy)
{
    const int r = blockIdx.x;
    quant_row_block<LEN>(src + (size_t)r * lds,
                         q1 + (size_t)r * LEN, q2 + (size_t)r * LEN,
                         scale + r, cpy ? cpy + (size_t)r * LEN : nullptr);
}

__global__ void __launch_bounds__(128) quant_wm1(
    const float* __restrict__ Wm1,
    int8_t* __restrict__ f1, int8_t* __restrict__ f2, float* __restrict__ sf,
    int8_t* __restrict__ t1, int8_t* __restrict__ t2, float* __restrict__ st)
{
    const int r = blockIdx.x;
    if (r < FF) {
        quant_row_block<512>(Wm1 + (size_t)r * 2 * D,
                             f1 + (size_t)r * D, f2 + (size_t)r * D, sf + r, nullptr);
    } else {
        const int rr = r - FF;
        quant_row_block<512>(Wm1 + D + (size_t)rr * 2 * D,
                             t1 + (size_t)rr * D, t2 + (size_t)rr * D, st + rr, nullptr);
    }
}

// ---------------------------------------------------------------------------
// int8 split tensor-core GEMM (IMMA m16n8k32), 128x128 tile, 512 threads
// (16 warps, 4x4 grid of 32x32 warp tiles), K-chunks of 128 B,
// 2-stage cp.async pipeline, ONE sync per chunk, 1 CTA/SM (16 warps).
// ---------------------------------------------------------------------------
#define AROW 144
#define A_TILE_B (128 * AROW)      // 18432
#define B_TILE_B (128 * AROW)      // 18432
#define ST_A1 0
#define ST_A2 A_TILE_B
#define ST_B1 (2 * A_TILE_B)
#define ST_B2 (2 * A_TILE_B + B_TILE_B)
#define STAGE_B (2 * A_TILE_B + 2 * B_TILE_B)   // 73728
#define IG_SMEM (2 * STAGE_B)                    // 147456

template <int MODE>
__global__ void __launch_bounds__(512, 1) ig_gemm(
    const int8_t* __restrict__ Aq1, const int8_t* __restrict__ Aq2,
    const float* __restrict__ sA, int lda,
    const int8_t* __restrict__ Bq1, const int8_t* __restrict__ Bq2,
    const float* __restrict__ sB, int ldb,
    const float* __restrict__ bias,
    float* __restrict__ C, int ldc, int K)
{
    extern __shared__ char smem[];
    const uint32_t sb = smem_u32(smem);
    const int tid = threadIdx.x;
    const int wid = tid >> 5, lane = tid & 31;
    const int wm = wid >> 2;              // 0..3 (32 rows)
    const int wn = wid & 3;               // 0..3 (32 cols)
    const int brow = blockIdx.y * 128;
    const int bcol = blockIdx.x * 128;

    // loader mapping: 1024 (row,16B-seg) pairs per array, 2 per thread
    int rowgA[2], segA[2], smoffA[2];
#pragma unroll
    for (int t = 0; t < 2; t++) {
        int sid = tid + (t << 9);
        rowgA[t] = sid >> 3;
        segA[t] = (sid & 7) * 16;
        smoffA[t] = rowgA[t] * AROW + segA[t];
    }

    const int8_t* pA1 = Aq1 + (size_t)brow * lda;
    const int8_t* pA2 = Aq2 + (size_t)brow * lda;
    const int8_t* pB1 = Bq1 + (size_t)bcol * ldb;
    const int8_t* pB2 = Bq2 + (size_t)bcol * ldb;

    const uint32_t a_loff = (uint32_t)((wm * 32 + (lane & 15)) * AROW + (lane >> 4) * 16);
    const uint32_t b_loff = (uint32_t)((wn * 32 + (lane & 7) + ((lane >> 4) << 3)) * AROW
                                       + ((lane >> 3) & 1) * 16);

    int acc1[2][4][4];
    int accx[2][4][4];
#pragma unroll
    for (int i = 0; i < 2; i++)
#pragma unroll
        for (int j = 0; j < 4; j++)
#pragma unroll
            for (int e = 0; e < 4; e++) { acc1[i][j][e] = 0; accx[i][j][e] = 0; }

    const int NC = K >> 7;   // 128-byte chunks

#define IG_ISSUE(snb, kc) do {                                           \
    const uint32_t _s = (snb);                                           \
    _Pragma("unroll")                                                    \
    for (int t = 0; t < 2; t++) {                                        \
        const int go = rowgA[t] * lda + segA[t] + (kc);                  \
        cp16(_s + ST_A1 + smoffA[t], pA1 + go);                          \
        cp16(_s + ST_A2 + smoffA[t], pA2 + go);                          \
        const int gob = rowgA[t] * ldb + segA[t] + (kc);                 \
        cp16(_s + ST_B1 + smoffA[t], pB1 + gob);                         \
        cp16(_s + ST_B2 + smoffA[t], pB2 + gob);                         \
    }                                                                    \
    cp_commit();                                                         \
} while (0)

    // Prologue: chunk 0 into stage 0
    IG_ISSUE(sb, 0);

    for (int c = 0; c < NC; c++) {
        cp_wait<0>();      // chunk c resident (only group in flight)
        __syncthreads();   // all warps done with compute(c-1); chunk c visible
        if (c + 1 < NC) {
            // stage (c+1)&1 == (c-1)&1, whose readers all passed the sync above
            IG_ISSUE(sb + ((c + 1) & 1) * STAGE_B, (c + 1) << 7);
        }

        const uint32_t base = sb + (c & 1) * STAGE_B;
#pragma unroll
        for (int kk = 0; kk < 4; kk++) {
            const uint32_t kb = kk * 32;
            uint32_t b1r[8], b2r[8];
#pragma unroll
            for (int j = 0; j < 2; j++) {
                ldmx4(&b1r[j * 4], base + ST_B1 + j * (16 * AROW) + kb + b_loff);
                ldmx4(&b2r[j * 4], base + ST_B2 + j * (16 * AROW) + kb + b_loff);
            }
#pragma unroll
            for (int i = 0; i < 2; i++) {
                uint32_t a1[4], a2[4];
                ldmx4(a1, base + ST_A1 + i * (16 * AROW) + kb + a_loff);
                ldmx4(a2, base + ST_A2 + i * (16 * AROW) + kb + a_loff);
#pragma unroll
                for (int jn = 0; jn < 4; jn++) {
                    const uint32_t* bp1 = &b1r[(jn >> 1) * 4 + (jn & 1) * 2];
                    const uint32_t* bp2 = &b2r[(jn >> 1) * 4 + (jn & 1) * 2];
                    imma(acc1[i][jn], a1, bp1);
                    imma(accx[i][jn], a1, bp2);
                    imma(accx[i][jn], a2, bp1);
                }
            }
        }
    }
#undef IG_ISSUE

    const int lm = lane >> 2;
    const int ln = (lane & 3) * 2;
    const float inv254 = 1.0f / 254.0f;
#pragma unroll
    for (int i = 0; i < 2; i++) {
        const int r0 = brow + wm * 32 + i * 16 + lm;
        const float sa0 = sA[r0];
        const float sa1 = sA[r0 + 8];
#pragma unroll
        for (int jn = 0; jn < 4; jn++) {
            const int n = bcol + wn * 32 + jn * 8 + ln;
            const float sb0 = sB[n], sb1 = sB[n + 1];
            const float b0 = bias ? bias[n] : 0.0f;
            const float b1 = bias ? bias[n + 1] : 0.0f;
            float d0 = sa0 * sb0 * ((float)acc1[i][jn][0] + (float)accx[i][jn][0] * inv254) + b0;
            float d1 = sa0 * sb1 * ((float)acc1[i][jn][1] + (float)accx[i][jn][1] * inv254) + b1;
            float d2 = sa1 * sb0 * ((float)acc1[i][jn][2] + (float)accx[i][jn][2] * inv254) + b0;
            float d3 = sa1 * sb1 * ((float)acc1[i][jn][3] + (float)accx[i][jn][3] * inv254) + b1;
            if (MODE == 1) {
                d0 = gelu_exact(d0); d1 = gelu_exact(d1);
                d2 = gelu_exact(d2); d3 = gelu_exact(d3);
            }
            *(float2*)(C + (size_t)r0 * ldc + n) = make_float2(d0, d1);
            *(float2*)(C + (size_t)(r0 + 8) * ldc + n) = make_float2(d2, d3);
        }
    }
}

// ---------------------------------------------------------------------------
// Attention: one block per (b,h). Vectorized float4 inner loops.
// ---------------------------------------------------------------------------
#define QS 68
#define ATT_SMEM ((64 * QS + 2 * 64 * 64) * 4)

__global__ void __launch_bounds__(256) attn_kernel(
    const float* __restrict__ qkv, float* __restrict__ out)
{
    extern __shared__ float asm_[];
    float* Qs = asm_;
    float* Kt = asm_ + 64 * QS;
    float* Vs = Kt + 64 * 64;

    const int bh = blockIdx.x;
    const int b = bh >> 3;
    const int h = bh & 7;
    const int tid = threadIdx.x;
    const float* base = qkv + (size_t)b * S * (3 * D) + h * HD;

    {
        const int r = tid >> 2;
        const int c0 = (tid & 3) * 16;
#pragma unroll
        for (int i = 0; i < 4; i++) {
            int c = c0 + i * 4;
            float4 qv = *(const float4*)(base + (size_t)r * (3 * D) + c);
            float4 kv = *(const float4*)(base + (size_t)r * (3 * D) + D + c);
            float4 vv = *(const float4*)(base + (size_t)r * (3 * D) + 2 * D + c);
            *(float4*)(&Qs[r * QS + c]) = qv;
            *(float4*)(&Vs[r * 64 + c]) = vv;
            Kt[(c + 0) * 64 + r] = kv.x; Kt[(c + 1) * 64 + r] = kv.y;
            Kt[(c + 2) * 64 + r] = kv.z; Kt[(c + 3) * 64 + r] = kv.w;
        }
    }
    __syncthreads();

    const int i = tid >> 2;
    const int j0 = (tid & 3) * 16;

    float sc[16];
#pragma unroll
    for (int e = 0; e < 16; e++) sc[e] = 0.0f;
#pragma unroll 8
    for (int d = 0; d < 64; d++) {
        float qv = Qs[i * QS + d];
        const float* kr = &Kt[d * 64 + j0];
        float4 k0 = *(const float4*)(kr);
        float4 k1 = *(const float4*)(kr + 4);
        float4 k2 = *(const float4*)(kr + 8);
        float4 k3 = *(const float4*)(kr + 12);
        sc[0] = fmaf(qv, k0.x, sc[0]);  sc[1] = fmaf(qv, k0.y, sc[1]);
        sc[2] = fmaf(qv, k0.z, sc[2]);  sc[3] = fmaf(qv, k0.w, sc[3]);
        sc[4] = fmaf(qv, k1.x, sc[4]);  sc[5] = fmaf(qv, k1.y, sc[5]);
        sc[6] = fmaf(qv, k1.z, sc[6]);  sc[7] = fmaf(qv, k1.w, sc[7]);
        sc[8] = fmaf(qv, k2.x, sc[8]);  sc[9] = fmaf(qv, k2.y, sc[9]);
        sc[10] = fmaf(qv, k2.z, sc[10]); sc[11] = fmaf(qv, k2.w, sc[11]);
        sc[12] = fmaf(qv, k3.x, sc[12]); sc[13] = fmaf(qv, k3.y, sc[13]);
        sc[14] = fmaf(qv, k3.z, sc[14]); sc[15] = fmaf(qv, k3.w, sc[15]);
    }
    __syncthreads();

    float* P = Qs;
#pragma unroll
    for (int e = 0; e < 4; e++) {
        float4 v = make_float4(sc[e * 4] * 0.125f, sc[e * 4 + 1] * 0.125f,
                               sc[e * 4 + 2] * 0.125f, sc[e * 4 + 3] * 0.125f);
        *(float4*)(&P[i * QS + j0 + e * 4]) = v;
    }
    __syncthreads();

    const int warp = tid >> 5, lane = tid & 31;
#pragma unroll
    for (int rr = 0; rr < 8; rr++) {
        int r = warp + rr * 8;
        float v0 = P[r * QS + lane], v1 = P[r * QS + lane + 32];
        float mx = fmaxf(v0, v1);
#pragma unroll
        for (int o = 16; o > 0; o >>= 1) mx = fmaxf(mx, __shfl_xor_sync(~0u, mx, o));
        float e0 = __expf(v0 - mx), e1 = __expf(v1 - mx);
        float ssum = e0 + e1;
#pragma unroll
        for (int o = 16; o > 0; o >>= 1) ssum += __shfl_xor_sync(~0u, ssum, o);
        float inv = 1.0f / ssum;
        P[r * QS + lane] = e0 * inv;
        P[r * QS + lane + 32] = e1 * inv;
    }
    __syncthreads();

    float o[16];
#pragma unroll
    for (int e = 0; e < 16; e++) o[e] = 0.0f;
#pragma unroll 8
    for (int j = 0; j < 64; j++) {
        float pv = P[i * QS + j];
        const float* vr = &Vs[j * 64 + j0];
        float4 v0 = *(const float4*)(vr);
        float4 v1 = *(const float4*)(vr + 4);
        float4 v2 = *(const float4*)(vr + 8);
        float4 v3 = *(const float4*)(vr + 12);
        o[0] = fmaf(pv, v0.x, o[0]);   o[1] = fmaf(pv, v0.y, o[1]);
        o[2] = fmaf(pv, v0.z, o[2]);   o[3] = fmaf(pv, v0.w, o[3]);
        o[4] = fmaf(pv, v1.x, o[4]);   o[5] = fmaf(pv, v1.y, o[5]);
        o[6] = fmaf(pv, v1.z, o[6]);   o[7] = fmaf(pv, v1.w, o[7]);
        o[8] = fmaf(pv, v2.x, o[8]);   o[9] = fmaf(pv, v2.y, o[9]);
        o[10] = fmaf(pv, v2.z, o[10]); o[11] = fmaf(pv, v2.w, o[11]);
        o[12] = fmaf(pv, v3.x, o[12]); o[13] = fmaf(pv, v3.y, o[13]);
        o[14] = fmaf(pv, v3.z, o[14]); o[15] = fmaf(pv, v3.w, o[15]);
    }
    float* orow = out + (size_t)(b * S + i) * D + h * HD + j0;
#pragma unroll
    for (int e = 0; e < 4; e++)
        *(float4*)(orow + e * 4) = make_float4(o[e * 4], o[e * 4 + 1],
                                               o[e * 4 + 2], o[e * 4 + 3]);
}

// ---------------------------------------------------------------------------
// Fused residual add + LayerNorm + quant
// ---------------------------------------------------------------------------
__global__ void __launch_bounds__(128) add_ln_kernel(
    float* __restrict__ x, const float* __restrict__ y,
    const float* __restrict__ g, const float* __restrict__ bta,
    int8_t* __restrict__ q1, int8_t* __restrict__ q2,
    float* __restrict__ scale)
{
    const int row = blockIdx.x;
    const int tid = threadIdx.x;
    const int warp = tid >> 5, lane = tid & 31;

    float4 xv = *(const float4*)(x + (size_t)row * D + tid * 4);
    float4 yv = *(const float4*)(y + (size_t)row * D + tid * 4);
    float s0 = xv.x + yv.x, s1v = xv.y + yv.y, s2 = xv.z + yv.z, s3 = xv.w + yv.w;

    float sum = s0 + s1v + s2 + s3;
    float sq = fmaf(s0, s0, fmaf(s1v, s1v, fmaf(s2, s2, s3 * s3)));
#pragma unroll
    for (int o = 16; o > 0; o >>= 1) {
        sum += __shfl_xor_sync(~0u, sum, o);
        sq  += __shfl_xor_sync(~0u, sq, o);
    }
    __shared__ float sh[8];
    __shared__ float smax[4];
    if (lane == 0) { sh[warp] = sum; sh[4 + warp] = sq; }
    __syncthreads();
    sum = sh[0] + sh[1] + sh[2] + sh[3];
    sq  = sh[4] + sh[5] + sh[6] + sh[7];

    const float mu = sum * (1.0f / D);
    const float var = sq * (1.0f / D) - mu * mu;
    const float inv = rsqrtf(var + EPS);

    float4 gv = *(const float4*)(g + tid * 4);
    float4 bv = *(const float4*)(bta + tid * 4);
    float o0 = (s0 - mu) * inv * gv.x + bv.x;
    float o1 = (s1v - mu) * inv * gv.y + bv.y;
    float o2 = (s2 - mu) * inv * gv.z + bv.z;
    float o3 = (s3 - mu) * inv * gv.w + bv.w;
    *(float4*)(x + (size_t)row * D + tid * 4) = make_float4(o0, o1, o2, o3);

    float m = fmaxf(fmaxf(fabsf(o0), fabsf(o1)), fmaxf(fabsf(o2), fabsf(o3)));
#pragma unroll
    for (int o = 16; o > 0; o >>= 1) m = fmaxf(m, __shfl_xor_sync(~0u, m, o));
    if (lane == 0) smax[warp] = m;
    __syncthreads();
    m = fmaxf(fmaxf(smax[0], smax[1]), fmaxf(smax[2], smax[3]));
    m = fmaxf(m, 1e-30f);

    const float s1q = m * (1.0f / 127.0f);
    const float i1 = 127.0f / m;
    const float i2 = 254.0f / s1q;
    if (tid == 0) scale[row] = s1q;

    float xs[4] = {o0, o1, o2, o3};
    int pk1 = 0, pk2 = 0;
#pragma unroll
    for (int e = 0; e < 4; e++) {
        int a = __float2int_rn(xs[e] * i1);
        float rr = xs[e] - s1q * (float)a;
        int b2 = __float2int_rn(rr * i2);
        b2 = max(-127, min(127, b2));
        pk1 |= (a & 255) << (8 * e);
        pk2 |= (b2 & 255) << (8 * e);
    }
    ((int*)(q1 + (size_t)row * D))[tid] = pk1;
    ((int*)(q2 + (size_t)row * D))[tid] = pk2;
}

// ---------------------------------------------------------------------------
// Pairwise policy head (tanh-gelu)
// ---------------------------------------------------------------------------
#define PCH 128

__global__ void __launch_bounds__(256) pairwise_kernel(
    const float* __restrict__ F, const float* __restrict__ T,
    const float* __restrict__ bm1, const float* __restrict__ wm2,
    const float* __restrict__ bm2v, float* __restrict__ out)
{
    const int b = blockIdx.x >> 3;
    const int ft = blockIdx.x & 7;

    __shared__ float Fs[8][PCH + 1];
    __shared__ float Ts[64][PCH + 1];
    __shared__ __align__(16) float ws[PCH];

    const int tid = threadIdx.x;
    const int f = tid & 7;
    const int t0 = (tid >> 3) * 2;

    float acc0 = 0.0f, acc1v = 0.0f;
    const float* Fbase = F + ((size_t)b * S + ft * 8) * FF;
    const float* Tbase = T + (size_t)b * S * FF;

    for (int c = 0; c < FF; c += PCH) {
        {
            int fr = tid >> 5, cc = (tid & 31) * 4;
            float4 fv = *(const float4*)(Fbase + (size_t)fr * FF + c + cc);
            Fs[fr][cc + 0] = fv.x; Fs[fr][cc + 1] = fv.y;
            Fs[fr][cc + 2] = fv.z; Fs[fr][cc + 3] = fv.w;
        }
        if (tid < 32) *(float4*)(&ws[tid * 4]) = *(const float4*)(wm2 + c + tid * 4);
        {
            int tr = tid >> 2, tcc0 = (tid & 3) * 32;
#pragma unroll
            for (int i = 0; i < 8; i++) {
                int cc = tcc0 + i * 4;
                float4 tv = *(const float4*)(Tbase + (size_t)tr * FF + c + cc);
                float4 bb = *(const float4*)(bm1 + c + cc);
                Ts[tr][cc + 0] = tv.x + bb.x;
                Ts[tr][cc + 1] = tv.y + bb.y;
                Ts[tr][cc + 2] = tv.z + bb.z;
                Ts[tr][cc + 3] = tv.w + bb.w;
            }
        }
        __syncthreads();

#pragma unroll 4
        for (int hh = 0; hh < PCH; hh++) {
            float fv = Fs[f][hh];
            float w = ws[hh];
            float a0 = fv + Ts[t0][hh];
            float a1 = fv + Ts[t0 + 1][hh];
            acc0  = fmaf(gelu_fast(a0), w, acc0);
            acc1v = fmaf(gelu_fast(a1), w, acc1v);
        }
        __syncthreads();
    }

    const float bm2s = bm2v[0];
    const int fg = ft * 8 + f;
    float* orow = out + ((size_t)b * S + fg) * S;
    orow[t0]     = acc0 + bm2s;
    orow[t0 + 1] = acc1v + bm2s;
}

// ---------------------------------------------------------------------------
// Launcher: QKV ig_gemm is OUR 4th launch (ncu -s 5 lands on harness+2 -> us+4)
// ---------------------------------------------------------------------------
extern "C" void kernel_launch(void* const* d_in, const int* in_sizes, int n_in,
                              void* d_out, int out_size)
{
    const float* emb   = (const float*)d_in[0];
    const float* Wqkv  = (const float*)d_in[1];
    const float* bqkv  = (const float*)d_in[2];
    const float* Wo    = (const float*)d_in[3];
    const float* bo    = (const float*)d_in[4];
    const float* ln1_g = (const float*)d_in[5];
    const float* ln1_b = (const float*)d_in[6];
    const float* ln2_g = (const float*)d_in[7];
    const float* ln2_b = (const float*)d_in[8];
    const float* W1    = (const float*)d_in[9];
    const float* b1    = (const float*)d_in[10];
    const float* W2    = (const float*)d_in[11];
    const float* b2    = (const float*)d_in[12];
    const float* Wm1   = (const float*)d_in[13];
    const float* bm1   = (const float*)d_in[14];
    const float* Wm2   = (const float*)d_in[15];
    const float* bm2   = (const float*)d_in[16];
    float* out = (float*)d_out;

    float *x, *qkvb, *ao, *tmp, *hb, *fb, *tb;
    cudaGetSymbolAddress((void**)&x, g_x);
    cudaGetSymbolAddress((void**)&qkvb, g_qkv);
    cudaGetSymbolAddress((void**)&ao, g_ao);
    cudaGetSymbolAddress((void**)&tmp, g_tmp);
    cudaGetSymbolAddress((void**)&hb, g_h);
    cudaGetSymbolAddress((void**)&fb, g_f);
    cudaGetSymbolAddress((void**)&tb, g_t);

    int8_t *x1, *x2, *ao1, *ao2, *h1, *h2;
    int8_t *wq1, *wq2, *wo1, *wo2, *w11, *w12, *w21, *w22, *mf1, *mf2, *mt1, *mt2;
    float *sx, *sao, *sh, *swq, *swo, *sw1, *sw2, *smf, *smt;
    cudaGetSymbolAddress((void**)&x1, q_x1);   cudaGetSymbolAddress((void**)&x2, q_x2);
    cudaGetSymbolAddress((void**)&ao1, q_ao1); cudaGetSymbolAddress((void**)&ao2, q_ao2);
    cudaGetSymbolAddress((void**)&h1, q_h1);   cudaGetSymbolAddress((void**)&h2, q_h2);
    cudaGetSymbolAddress((void**)&wq1, q_wqkv1); cudaGetSymbolAddress((void**)&wq2, q_wqkv2);
    cudaGetSymbolAddress((void**)&wo1, q_wo1); cudaGetSymbolAddress((void**)&wo2, q_wo2);
    cudaGetSymbolAddress((void**)&w11, q_w11); cudaGetSymbolAddress((void**)&w12, q_w12);
    cudaGetSymbolAddress((void**)&w21, q_w21); cudaGetSymbolAddress((void**)&w22, q_w22);
    cudaGetSymbolAddress((void**)&mf1, q_wm1f1); cudaGetSymbolAddress((void**)&mf2, q_wm1f2);
    cudaGetSymbolAddress((void**)&mt1, q_wm1t1); cudaGetSymbolAddress((void**)&mt2, q_wm1t2);
    cudaGetSymbolAddress((void**)&sx, s_x);    cudaGetSymbolAddress((void**)&sao, s_ao);
    cudaGetSymbolAddress((void**)&sh, s_h);    cudaGetSymbolAddress((void**)&swq, s_wqkv);
    cudaGetSymbolAddress((void**)&swo, s_wo);  cudaGetSymbolAddress((void**)&sw1, s_w1);
    cudaGetSymbolAddress((void**)&sw2, s_w2);  cudaGetSymbolAddress((void**)&smf, s_wm1f);
    cudaGetSymbolAddress((void**)&smt, s_wm1t);

    cudaFuncSetAttribute(ig_gemm<0>, cudaFuncAttributeMaxDynamicSharedMemorySize, IG_SMEM);
    cudaFuncSetAttribute(ig_gemm<1>, cudaFuncAttributeMaxDynamicSharedMemorySize, IG_SMEM);
    cudaFuncSetAttribute(attn_kernel, cudaFuncAttributeMaxDynamicSharedMemorySize, ATT_SMEM);

    const dim3 gQKV(3 * D / 128, M_TOT / 128);   // (12, 32)
    const dim3 gD  (D / 128,     M_TOT / 128);   // (4, 32)
    const dim3 gFF (FF / 128,    M_TOT / 128);   // (8, 32)

    // Launch order: our #4 is the layer-0 QKV GEMM (ncu capture target).
    quant_rows<512><<<LAYERS * 3 * D, 128>>>(Wqkv, D, wq1, wq2, swq, nullptr);   // 1
    quant_rows<512><<<M_TOT, 128>>>(emb, D, x1, x2, sx, x);                      // 2 (also emb->g_x)
    quant_rows<512><<<LAYERS * D, 128>>>(Wo, D, wo1, wo2, swo, nullptr);         // 3

    for (int l = 0; l < LAYERS; l++) {
        ig_gemm<0><<<gQKV, 512, IG_SMEM>>>(                                       // 4 on l=0
            x1, x2, sx, D,
            wq1 + (size_t)l * 3 * D * D, wq2 + (size_t)l * 3 * D * D,
            swq + (size_t)l * 3 * D, D,
            bqkv + (size_t)l * 3 * D, qkvb, 3 * D, D);
        attn_kernel<<<B * H, 256, ATT_SMEM>>>(qkvb, ao);
        if (l == 0) {
            quant_rows<512><<<LAYERS * FF, 128>>>(W1, D, w11, w12, sw1, nullptr);
            quant_rows<1024><<<LAYERS * D, 128>>>(W2, FF, w21, w22, sw2, nullptr);
        }
        quant_rows<512><<<M_TOT, 128>>>(ao, D, ao1, ao2, sao, nullptr);
        ig_gemm<0><<<gD, 512, IG_SMEM>>>(
            ao1, ao2, sao, D,
            wo1 + (size_t)l * D * D, wo2 + (size_t)l * D * D,
            swo + (size_t)l * D, D,
            bo + (size_t)l * D, tmp, D, D);
        add_ln_kernel<<<M_TOT, 128>>>(x, tmp, ln1_g + (size_t)l * D,
                                      ln1_b + (size_t)l * D, x1, x2, sx);
        ig_gemm<1><<<gFF, 512, IG_SMEM>>>(
            x1, x2, sx, D,
            w11 + (size_t)l * FF * D, w12 + (size_t)l * FF * D,
            sw1 + (size_t)l * FF, D,
            b1 + (size_t)l * FF, hb, FF, D);
        quant_rows<1024><<<M_TOT, 128>>>(hb, FF, h1, h2, sh, nullptr);
        ig_gemm<0><<<gD, 512, IG_SMEM>>>(
            h1, h2, sh, FF,
            w21 + (size_t)l * D * FF, w22 + (size_t)l * D * FF,
            sw2 + (size_t)l * D, FF,
            b2 + (size_t)l * D, tmp, D, FF);
        add_ln_kernel<<<M_TOT, 128>>>(x, tmp, ln2_g + (size_t)l * D,
                                      ln2_b + (size_t)l * D, x1, x2, sx);
    }

    quant_wm1<<<2 * FF, 128>>>(Wm1, mf1, mf2, smf, mt1, mt2, smt);
    ig_gemm<0><<<gFF, 512, IG_SMEM>>>(
        x1, x2, sx, D, mf1, mf2, smf, D, nullptr, fb, FF, D);
    ig_gemm<0><<<gFF, 512, IG_SMEM>>>(
        x1, x2, sx, D, mt1, mt2, smt, D, nullptr, tb, FF, D);
    pairwise_kernel<<<B * 8, 256>>>(fb, tb, bm1, Wm2, bm2, out);
}

// round 15
// speedup vs baseline: 1.0321x; 1.0321x over previous
#include <cuda_runtime.h>
#include <cuda_bf16.h>
#include <math.h>
#include <stdint.h>

#define LAYERS 4
#define D 512
#define H 8
#define HD 64
#define FF 1024
#define B 64
#define S 64
#define M_TOT (B * S)
#define EPS 1e-5f

// ---------------------------------------------------------------------------
// Scratch buffers
// ---------------------------------------------------------------------------
__device__ float g_x[M_TOT * D];
__device__ float g_qkv[M_TOT * 3 * D];
__device__ float g_ao[M_TOT * D];
__device__ float g_tmp[M_TOT * D];
__device__ float g_h[M_TOT * FF];
__device__ float g_f[M_TOT * FF];
__device__ float g_t[M_TOT * FF];

__device__ int8_t q_x1[M_TOT * D],  q_x2[M_TOT * D];
__device__ int8_t q_ao1[M_TOT * D], q_ao2[M_TOT * D];
__device__ int8_t q_h1[M_TOT * FF], q_h2[M_TOT * FF];
__device__ int8_t q_wqkv1[LAYERS * 3 * D * D], q_wqkv2[LAYERS * 3 * D * D];
__device__ int8_t q_wo1[LAYERS * D * D],       q_wo2[LAYERS * D * D];
__device__ int8_t q_w11[LAYERS * FF * D],      q_w12[LAYERS * FF * D];
__device__ int8_t q_w21[LAYERS * D * FF],      q_w22[LAYERS * D * FF];
__device__ int8_t q_wm1f1[FF * D], q_wm1f2[FF * D];
__device__ int8_t q_wm1t1[FF * D], q_wm1t2[FF * D];

__device__ float s_x[M_TOT], s_ao[M_TOT], s_h[M_TOT];
__device__ float s_wqkv[LAYERS * 3 * D], s_wo[LAYERS * D];
__device__ float s_w1[LAYERS * FF], s_w2[LAYERS * D];
__device__ float s_wm1f[FF], s_wm1t[FF];

// ---------------------------------------------------------------------------
// Helpers
// ---------------------------------------------------------------------------
__device__ __forceinline__ float gelu_exact(float x) {
    return 0.5f * x * (1.0f + erff(x * 0.70710678118654752f));
}
__device__ __forceinline__ float tanh_fast(float x) {
    float y;
    asm("tanh.approx.f32 %0, %1;" : "=f"(y) : "f"(x));
    return y;
}
__device__ __forceinline__ float gelu_fast(float x) {
    float u = x * x;
    float z = x * fmaf(0.0356774081f, u, 0.7978845608f);
    float th = tanh_fast(z);
    float hx = 0.5f * x;
    return fmaf(hx, th, hx);
}
__device__ __forceinline__ uint32_t smem_u32(const void* p) {
    uint32_t a;
    asm("{ .reg .u64 t; cvta.to.shared.u64 t, %1; cvt.u32.u64 %0, t; }"
        : "=r"(a) : "l"(p));
    return a;
}
__device__ __forceinline__ void ldmx4(uint32_t* r, uint32_t addr) {
    asm volatile("ldmatrix.sync.aligned.m8n8.x4.shared.b16 {%0,%1,%2,%3}, [%4];"
                 : "=r"(r[0]), "=r"(r[1]), "=r"(r[2]), "=r"(r[3]) : "r"(addr));
}
__device__ __forceinline__ void imma(int* d, const uint32_t* a, const uint32_t* b) {
    asm volatile(
        "mma.sync.aligned.m16n8k32.row.col.s32.s8.s8.s32 "
        "{%0,%1,%2,%3}, {%4,%5,%6,%7}, {%8,%9}, {%0,%1,%2,%3};"
        : "+r"(d[0]), "+r"(d[1]), "+r"(d[2]), "+r"(d[3])
        : "r"(a[0]), "r"(a[1]), "r"(a[2]), "r"(a[3]), "r"(b[0]), "r"(b[1]));
}
__device__ __forceinline__ void cp16(uint32_t saddr, const void* gptr) {
    asm volatile("cp.async.cg.shared.global [%0], [%1], 16;"
                 :: "r"(saddr), "l"(gptr));
}
__device__ __forceinline__ void cp_commit() {
    asm volatile("cp.async.commit_group;");
}
template <int N>
__device__ __forceinline__ void cp_wait() {
    asm volatile("cp.async.wait_group %0;" :: "n"(N));
}

// ---------------------------------------------------------------------------
// Block-level (128 threads) two-level int8 row quantization
// ---------------------------------------------------------------------------
template <int LEN>
__device__ __forceinline__ void quant_row_block(
    const float* __restrict__ src, int8_t* __restrict__ q1row,
    int8_t* __restrict__ q2row, float* __restrict__ scale_slot,
    float* __restrict__ cpy)
{
    const int tid = threadIdx.x;
    const int warp = tid >> 5, lane = tid & 31;
    float4 v[LEN / 512];
    float m = 0.0f;
#pragma unroll
    for (int p = 0; p < LEN / 512; p++) {
        v[p] = *((const float4*)src + p * 128 + tid);
        m = fmaxf(m, fmaxf(fmaxf(fabsf(v[p].x), fabsf(v[p].y)),
                           fmaxf(fabsf(v[p].z), fabsf(v[p].w))));
    }
#pragma unroll
    for (int o = 16; o > 0; o >>= 1) m = fmaxf(m, __shfl_xor_sync(~0u, m, o));
    __shared__ float sm[4];
    if (lane == 0) sm[warp] = m;
    __syncthreads();
    m = fmaxf(fmaxf(sm[0], sm[1]), fmaxf(sm[2], sm[3]));
    m = fmaxf(m, 1e-30f);

    const float s1 = m * (1.0f / 127.0f);
    const float i1 = 127.0f / m;
    const float i2 = 254.0f / s1;
    if (tid == 0) *scale_slot = s1;

    int* q1p = (int*)q1row;
    int* q2p = (int*)q2row;
#pragma unroll
    for (int p = 0; p < LEN / 512; p++) {
        float xs[4] = {v[p].x, v[p].y, v[p].z, v[p].w};
        int pk1 = 0, pk2 = 0;
#pragma unroll
        for (int e = 0; e < 4; e++) {
            int a = __float2int_rn(xs[e] * i1);
            float r = xs[e] - s1 * (float)a;
            int b2 = __float2int_rn(r * i2);
            b2 = max(-127, min(127, b2));
            pk1 |= (a & 255) << (8 * e);
            pk2 |= (b2 & 255) << (8 * e);
        }
        q1p[p * 128 + tid] = pk1;
        q2p[p * 128 + tid] = pk2;
        if (cpy) *((float4*)cpy + p * 128 + tid) = v[p];
    }
}

template <int LEN>
__global__ void __launch_bounds__(128) quant_rows(
    const float* __restrict__ src, int lds,
    int8_t* __restrict__ q1, int8_t* __restrict__ q2,
    float* __restrict__ scale, float* __restrict__ cpy)
{
    const int r = blockIdx.x;
    quant_row_block<LEN>(src + (size_t)r * lds,
                         q1 + (size_t)r * LEN, q2 + (size_t)r * LEN,
                         scale + r, cpy ? cpy + (size_t)r * LEN : nullptr);
}

__global__ void __launch_bounds__(128) quant_wm1(
    const float* __restrict__ Wm1,
    int8_t* __restrict__ f1, int8_t* __restrict__ f2, float* __restrict__ sf,
    int8_t* __restrict__ t1, int8_t* __restrict__ t2, float* __restrict__ st)
{
    const int r = blockIdx.x;
    if (r < FF) {
        quant_row_block<512>(Wm1 + (size_t)r * 2 * D,
                             f1 + (size_t)r * D, f2 + (size_t)r * D, sf + r, nullptr);
    } else {
        const int rr = r - FF;
        quant_row_block<512>(Wm1 + D + (size_t)rr * 2 * D,
                             t1 + (size_t)rr * D, t2 + (size_t)rr * D, st + rr, nullptr);
    }
}

// ---------------------------------------------------------------------------
// int8 split tensor-core GEMM (IMMA m16n8k32), 128x64 tile,
// K-chunks of 128 B, 2-stage cp.async pipeline, ONE sync per chunk,
// 2 CTAs/SM.  (Best validated config: R12, 39.4us QKV.)
// ---------------------------------------------------------------------------
#define AROW 144
#define A_TILE_B (128 * AROW)      // 18432
#define B_TILE_B (64 * AROW)       // 9216
#define ST_A1 0
#define ST_A2 A_TILE_B
#define ST_B1 (2 * A_TILE_B)
#define ST_B2 (2 * A_TILE_B + B_TILE_B)
#define STAGE_B (2 * A_TILE_B + 2 * B_TILE_B)   // 55296
#define IG_SMEM (2 * STAGE_B)                    // 110592

template <int MODE>
__global__ void __launch_bounds__(256, 2) ig_gemm(
    const int8_t* __restrict__ Aq1, const int8_t* __restrict__ Aq2,
    const float* __restrict__ sA, int lda,
    const int8_t* __restrict__ Bq1, const int8_t* __restrict__ Bq2,
    const float* __restrict__ sB, int ldb,
    const float* __restrict__ bias,
    float* __restrict__ C, int ldc, int K)
{
    extern __shared__ char smem[];
    const uint32_t sb = smem_u32(smem);
    const int tid = threadIdx.x;
    const int wid = tid >> 5, lane = tid & 31;
    const int wm = wid >> 1;              // 0..3 (32 rows)
    const int wn = wid & 1;               // 0..1 (32 cols)
    const int brow = blockIdx.y * 128;
    const int bcol = blockIdx.x * 64;

    int rowgA[4], segA[4], smoffA[4];
#pragma unroll
    for (int t = 0; t < 4; t++) {
        int sid = tid + (t << 8);
        rowgA[t] = sid >> 3;
        segA[t] = (sid & 7) * 16;
        smoffA[t] = rowgA[t] * AROW + segA[t];
    }
    int rowgB[2], segB[2], smoffB[2];
#pragma unroll
    for (int t = 0; t < 2; t++) {
        int sid = tid + (t << 8);
        rowgB[t] = sid >> 3;
        segB[t] = (sid & 7) * 16;
        smoffB[t] = rowgB[t] * AROW + segB[t];
    }

    const int8_t* pA1 = Aq1 + (size_t)brow * lda;
    const int8_t* pA2 = Aq2 + (size_t)brow * lda;
    const int8_t* pB1 = Bq1 + (size_t)bcol * ldb;
    const int8_t* pB2 = Bq2 + (size_t)bcol * ldb;

    const uint32_t a_loff = (uint32_t)((wm * 32 + (lane & 15)) * AROW + (lane >> 4) * 16);
    const uint32_t b_loff = (uint32_t)((wn * 32 + (lane & 7) + ((lane >> 4) << 3)) * AROW
                                       + ((lane >> 3) & 1) * 16);

    int acc1[2][4][4];
    int accx[2][4][4];
#pragma unroll
    for (int i = 0; i < 2; i++)
#pragma unroll
        for (int j = 0; j < 4; j++)
#pragma unroll
            for (int e = 0; e < 4; e++) { acc1[i][j][e] = 0; accx[i][j][e] = 0; }

    const int NC = K >> 7;   // 128-byte chunks

#define IG_ISSUE(snb, kc) do {                                           \
    const uint32_t _s = (snb);                                           \
    _Pragma("unroll")                                                    \
    for (int t = 0; t < 4; t++) {                                        \
        const int go = rowgA[t] * lda + segA[t] + (kc);                  \
        cp16(_s + ST_A1 + smoffA[t], pA1 + go);                          \
        cp16(_s + ST_A2 + smoffA[t], pA2 + go);                          \
    }                                                                    \
    _Pragma("unroll")                                                    \
    for (int t = 0; t < 2; t++) {                                        \
        const int gob = rowgB[t] * ldb + segB[t] + (kc);                 \
        cp16(_s + ST_B1 + smoffB[t], pB1 + gob);                         \
        cp16(_s + ST_B2 + smoffB[t], pB2 + gob);                         \
    }                                                                    \
    cp_commit();                                                         \
} while (0)

    // Prologue: chunk 0 into stage 0
    IG_ISSUE(sb, 0);

    for (int c = 0; c < NC; c++) {
        cp_wait<0>();      // chunk c resident (only group in flight)
        __syncthreads();   // all warps done with compute(c-1); chunk c visible
        if (c + 1 < NC) {
            IG_ISSUE(sb + ((c + 1) & 1) * STAGE_B, (c + 1) << 7);
        }

        const uint32_t base = sb + (c & 1) * STAGE_B;
#pragma unroll
        for (int kk = 0; kk < 4; kk++) {
            const uint32_t kb = kk * 32;
            uint32_t b1r[8], b2r[8];
#pragma unroll
            for (int j = 0; j < 2; j++) {
                ldmx4(&b1r[j * 4], base + ST_B1 + j * (16 * AROW) + kb + b_loff);
                ldmx4(&b2r[j * 4], base + ST_B2 + j * (16 * AROW) + kb + b_loff);
            }
#pragma unroll
            for (int i = 0; i < 2; i++) {
                uint32_t a1[4], a2[4];
                ldmx4(a1, base + ST_A1 + i * (16 * AROW) + kb + a_loff);
                ldmx4(a2, base + ST_A2 + i * (16 * AROW) + kb + a_loff);
#pragma unroll
                for (int jn = 0; jn < 4; jn++) {
                    const uint32_t* bp1 = &b1r[(jn >> 1) * 4 + (jn & 1) * 2];
                    const uint32_t* bp2 = &b2r[(jn >> 1) * 4 + (jn & 1) * 2];
                    imma(acc1[i][jn], a1, bp1);
                    imma(accx[i][jn], a1, bp2);
                    imma(accx[i][jn], a2, bp1);
                }
            }
        }
    }
#undef IG_ISSUE

    const int lm = lane >> 2;
    const int ln = (lane & 3) * 2;
    const float inv254 = 1.0f / 254.0f;
#pragma unroll
    for (int i = 0; i < 2; i++) {
        const int r0 = brow + wm * 32 + i * 16 + lm;
        const float sa0 = sA[r0];
        const float sa1 = sA[r0 + 8];
#pragma unroll
        for (int jn = 0; jn < 4; jn++) {
            const int n = bcol + wn * 32 + jn * 8 + ln;
            const float sb0 = sB[n], sb1 = sB[n + 1];
            const float b0 = bias ? bias[n] : 0.0f;
            const float b1 = bias ? bias[n + 1] : 0.0f;
            float d0 = sa0 * sb0 * ((float)acc1[i][jn][0] + (float)accx[i][jn][0] * inv254) + b0;
            float d1 = sa0 * sb1 * ((float)acc1[i][jn][1] + (float)accx[i][jn][1] * inv254) + b1;
            float d2 = sa1 * sb0 * ((float)acc1[i][jn][2] + (float)accx[i][jn][2] * inv254) + b0;
            float d3 = sa1 * sb1 * ((float)acc1[i][jn][3] + (float)accx[i][jn][3] * inv254) + b1;
            if (MODE == 1) {
                d0 = gelu_exact(d0); d1 = gelu_exact(d1);
                d2 = gelu_exact(d2); d3 = gelu_exact(d3);
            }
            *(float2*)(C + (size_t)r0 * ldc + n) = make_float2(d0, d1);
            *(float2*)(C + (size_t)(r0 + 8) * ldc + n) = make_float2(d2, d3);
        }
    }
}

// ---------------------------------------------------------------------------
// Attention: one block per (b,h). Vectorized float4 inner loops.
// ---------------------------------------------------------------------------
#define QS 68
#define ATT_SMEM ((64 * QS + 2 * 64 * 64) * 4)

__global__ void __launch_bounds__(256) attn_kernel(
    const float* __restrict__ qkv, float* __restrict__ out)
{
    extern __shared__ float asm_[];
    float* Qs = asm_;
    float* Kt = asm_ + 64 * QS;
    float* Vs = Kt + 64 * 64;

    const int bh = blockIdx.x;
    const int b = bh >> 3;
    const int h = bh & 7;
    const int tid = threadIdx.x;
    const float* base = qkv + (size_t)b * S * (3 * D) + h * HD;

    {
        const int r = tid >> 2;
        const int c0 = (tid & 3) * 16;
#pragma unroll
        for (int i = 0; i < 4; i++) {
            int c = c0 + i * 4;
            float4 qv = *(const float4*)(base + (size_t)r * (3 * D) + c);
            float4 kv = *(const float4*)(base + (size_t)r * (3 * D) + D + c);
            float4 vv = *(const float4*)(base + (size_t)r * (3 * D) + 2 * D + c);
            *(float4*)(&Qs[r * QS + c]) = qv;
            *(float4*)(&Vs[r * 64 + c]) = vv;
            Kt[(c + 0) * 64 + r] = kv.x; Kt[(c + 1) * 64 + r] = kv.y;
            Kt[(c + 2) * 64 + r] = kv.z; Kt[(c + 3) * 64 + r] = kv.w;
        }
    }
    __syncthreads();

    const int i = tid >> 2;
    const int j0 = (tid & 3) * 16;

    float sc[16];
#pragma unroll
    for (int e = 0; e < 16; e++) sc[e] = 0.0f;
#pragma unroll 8
    for (int d = 0; d < 64; d++) {
        float qv = Qs[i * QS + d];
        const float* kr = &Kt[d * 64 + j0];
        float4 k0 = *(const float4*)(kr);
        float4 k1 = *(const float4*)(kr + 4);
        float4 k2 = *(const float4*)(kr + 8);
        float4 k3 = *(const float4*)(kr + 12);
        sc[0] = fmaf(qv, k0.x, sc[0]);  sc[1] = fmaf(qv, k0.y, sc[1]);
        sc[2] = fmaf(qv, k0.z, sc[2]);  sc[3] = fmaf(qv, k0.w, sc[3]);
        sc[4] = fmaf(qv, k1.x, sc[4]);  sc[5] = fmaf(qv, k1.y, sc[5]);
        sc[6] = fmaf(qv, k1.z, sc[6]);  sc[7] = fmaf(qv, k1.w, sc[7]);
        sc[8] = fmaf(qv, k2.x, sc[8]);  sc[9] = fmaf(qv, k2.y, sc[9]);
        sc[10] = fmaf(qv, k2.z, sc[10]); sc[11] = fmaf(qv, k2.w, sc[11]);
        sc[12] = fmaf(qv, k3.x, sc[12]); sc[13] = fmaf(qv, k3.y, sc[13]);
        sc[14] = fmaf(qv, k3.z, sc[14]); sc[15] = fmaf(qv, k3.w, sc[15]);
    }
    __syncthreads();

    float* P = Qs;
#pragma unroll
    for (int e = 0; e < 4; e++) {
        float4 v = make_float4(sc[e * 4] * 0.125f, sc[e * 4 + 1] * 0.125f,
                               sc[e * 4 + 2] * 0.125f, sc[e * 4 + 3] * 0.125f);
        *(float4*)(&P[i * QS + j0 + e * 4]) = v;
    }
    __syncthreads();

    const int warp = tid >> 5, lane = tid & 31;
#pragma unroll
    for (int rr = 0; rr < 8; rr++) {
        int r = warp + rr * 8;
        float v0 = P[r * QS + lane], v1 = P[r * QS + lane + 32];
        float mx = fmaxf(v0, v1);
#pragma unroll
        for (int o = 16; o > 0; o >>= 1) mx = fmaxf(mx, __shfl_xor_sync(~0u, mx, o));
        float e0 = __expf(v0 - mx), e1 = __expf(v1 - mx);
        float ssum = e0 + e1;
#pragma unroll
        for (int o = 16; o > 0; o >>= 1) ssum += __shfl_xor_sync(~0u, ssum, o);
        float inv = 1.0f / ssum;
        P[r * QS + lane] = e0 * inv;
        P[r * QS + lane + 32] = e1 * inv;
    }
    __syncthreads();

    float o[16];
#pragma unroll
    for (int e = 0; e < 16; e++) o[e] = 0.0f;
#pragma unroll 8
    for (int j = 0; j < 64; j++) {
        float pv = P[i * QS + j];
        const float* vr = &Vs[j * 64 + j0];
        float4 v0 = *(const float4*)(vr);
        float4 v1 = *(const float4*)(vr + 4);
        float4 v2 = *(const float4*)(vr + 8);
        float4 v3 = *(const float4*)(vr + 12);
        o[0] = fmaf(pv, v0.x, o[0]);   o[1] = fmaf(pv, v0.y, o[1]);
        o[2] = fmaf(pv, v0.z, o[2]);   o[3] = fmaf(pv, v0.w, o[3]);
        o[4] = fmaf(pv, v1.x, o[4]);   o[5] = fmaf(pv, v1.y, o[5]);
        o[6] = fmaf(pv, v1.z, o[6]);   o[7] = fmaf(pv, v1.w, o[7]);
        o[8] = fmaf(pv, v2.x, o[8]);   o[9] = fmaf(pv, v2.y, o[9]);
        o[10] = fmaf(pv, v2.z, o[10]); o[11] = fmaf(pv, v2.w, o[11]);
        o[12] = fmaf(pv, v3.x, o[12]); o[13] = fmaf(pv, v3.y, o[13]);
        o[14] = fmaf(pv, v3.z, o[14]); o[15] = fmaf(pv, v3.w, o[15]);
    }
    float* orow = out + (size_t)(b * S + i) * D + h * HD + j0;
#pragma unroll
    for (int e = 0; e < 4; e++)
        *(float4*)(orow + e * 4) = make_float4(o[e * 4], o[e * 4 + 1],
                                               o[e * 4 + 2], o[e * 4 + 3]);
}

// ---------------------------------------------------------------------------
// Fused residual add + LayerNorm + quant
// ---------------------------------------------------------------------------
__global__ void __launch_bounds__(128) add_ln_kernel(
    float* __restrict__ x, const float* __restrict__ y,
    const float* __restrict__ g, const float* __restrict__ bta,
    int8_t* __restrict__ q1, int8_t* __restrict__ q2,
    float* __restrict__ scale)
{
    const int row = blockIdx.x;
    const int tid = threadIdx.x;
    const int warp = tid >> 5, lane = tid & 31;

    float4 xv = *(const float4*)(x + (size_t)row * D + tid * 4);
    float4 yv = *(const float4*)(y + (size_t)row * D + tid * 4);
    float s0 = xv.x + yv.x, s1v = xv.y + yv.y, s2 = xv.z + yv.z, s3 = xv.w + yv.w;

    float sum = s0 + s1v + s2 + s3;
    float sq = fmaf(s0, s0, fmaf(s1v, s1v, fmaf(s2, s2, s3 * s3)));
#pragma unroll
    for (int o = 16; o > 0; o >>= 1) {
        sum += __shfl_xor_sync(~0u, sum, o);
        sq  += __shfl_xor_sync(~0u, sq, o);
    }
    __shared__ float sh[8];
    __shared__ float smax[4];
    if (lane == 0) { sh[warp] = sum; sh[4 + warp] = sq; }
    __syncthreads();
    sum = sh[0] + sh[1] + sh[2] + sh[3];
    sq  = sh[4] + sh[5] + sh[6] + sh[7];

    const float mu = sum * (1.0f / D);
    const float var = sq * (1.0f / D) - mu * mu;
    const float inv = rsqrtf(var + EPS);

    float4 gv = *(const float4*)(g + tid * 4);
    float4 bv = *(const float4*)(bta + tid * 4);
    float o0 = (s0 - mu) * inv * gv.x + bv.x;
    float o1 = (s1v - mu) * inv * gv.y + bv.y;
    float o2 = (s2 - mu) * inv * gv.z + bv.z;
    float o3 = (s3 - mu) * inv * gv.w + bv.w;
    *(float4*)(x + (size_t)row * D + tid * 4) = make_float4(o0, o1, o2, o3);

    float m = fmaxf(fmaxf(fabsf(o0), fabsf(o1)), fmaxf(fabsf(o2), fabsf(o3)));
#pragma unroll
    for (int o = 16; o > 0; o >>= 1) m = fmaxf(m, __shfl_xor_sync(~0u, m, o));
    if (lane == 0) smax[warp] = m;
    __syncthreads();
    m = fmaxf(fmaxf(smax[0], smax[1]), fmaxf(smax[2], smax[3]));
    m = fmaxf(m, 1e-30f);

    const float s1q = m * (1.0f / 127.0f);
    const float i1 = 127.0f / m;
    const float i2 = 254.0f / s1q;
    if (tid == 0) scale[row] = s1q;

    float xs[4] = {o0, o1, o2, o3};
    int pk1 = 0, pk2 = 0;
#pragma unroll
    for (int e = 0; e < 4; e++) {
        int a = __float2int_rn(xs[e] * i1);
        float rr = xs[e] - s1q * (float)a;
        int b2 = __float2int_rn(rr * i2);
        b2 = max(-127, min(127, b2));
        pk1 |= (a & 255) << (8 * e);
        pk2 |= (b2 & 255) << (8 * e);
    }
    ((int*)(q1 + (size_t)row * D))[tid] = pk1;
    ((int*)(q2 + (size_t)row * D))[tid] = pk2;
}

// ---------------------------------------------------------------------------
// Pairwise policy head (tanh-gelu), float4-vectorized inner loop.
// Ts/Fs rows padded to stride 132 (mult of 4 -> aligned LDS.128; 8 lanes
// share t0 -> Ts broadcast; f rows 4 banks apart -> conflict-free).
// ---------------------------------------------------------------------------
#define PCH 128
#define TSTR 132

__global__ void __launch_bounds__(256) pairwise_kernel(
    const float* __restrict__ F, const float* __restrict__ T,
    const float* __restrict__ bm1, const float* __restrict__ wm2,
    const float* __restrict__ bm2v, float* __restrict__ out)
{
    const int b = blockIdx.x >> 3;
    const int ft = blockIdx.x & 7;

    __shared__ __align__(16) float Fs[8 * TSTR];
    __shared__ __align__(16) float Ts[64 * TSTR];
    __shared__ __align__(16) float ws[PCH];

    const int tid = threadIdx.x;
    const int f = tid & 7;
    const int t0 = (tid >> 3) * 2;

    float acc0 = 0.0f, acc1v = 0.0f;
    const float* Fbase = F + ((size_t)b * S + ft * 8) * FF;
    const float* Tbase = T + (size_t)b * S * FF;

    for (int c = 0; c < FF; c += PCH) {
        {
            int fr = tid >> 5, cc = (tid & 31) * 4;
            float4 fv = *(const float4*)(Fbase + (size_t)fr * FF + c + cc);
            *(float4*)(&Fs[fr * TSTR + cc]) = fv;
        }
        if (tid < 32) *(float4*)(&ws[tid * 4]) = *(const float4*)(wm2 + c + tid * 4);
        {
            int tr = tid >> 2, tcc0 = (tid & 3) * 32;
#pragma unroll
            for (int i = 0; i < 8; i++) {
                int cc = tcc0 + i * 4;
                float4 tv = *(const float4*)(Tbase + (size_t)tr * FF + c + cc);
                float4 bb = *(const float4*)(bm1 + c + cc);
                float4 sv = make_float4(tv.x + bb.x, tv.y + bb.y,
                                        tv.z + bb.z, tv.w + bb.w);
                *(float4*)(&Ts[tr * TSTR + cc]) = sv;
            }
        }
        __syncthreads();

        const float* fr = &Fs[f * TSTR];
        const float* ta = &Ts[t0 * TSTR];
        const float* tb = &Ts[(t0 + 1) * TSTR];
#pragma unroll 8
        for (int hh = 0; hh < PCH; hh += 4) {
            float4 w4 = *(const float4*)(&ws[hh]);
            float4 f4 = *(const float4*)(fr + hh);
            float4 a4 = *(const float4*)(ta + hh);
            float4 b4 = *(const float4*)(tb + hh);
            acc0  = fmaf(gelu_fast(f4.x + a4.x), w4.x, acc0);
            acc0  = fmaf(gelu_fast(f4.y + a4.y), w4.y, acc0);
            acc0  = fmaf(gelu_fast(f4.z + a4.z), w4.z, acc0);
            acc0  = fmaf(gelu_fast(f4.w + a4.w), w4.w, acc0);
            acc1v = fmaf(gelu_fast(f4.x + b4.x), w4.x, acc1v);
            acc1v = fmaf(gelu_fast(f4.y + b4.y), w4.y, acc1v);
            acc1v = fmaf(gelu_fast(f4.z + b4.z), w4.z, acc1v);
            acc1v = fmaf(gelu_fast(f4.w + b4.w), w4.w, acc1v);
        }
        __syncthreads();
    }

    const float bm2s = bm2v[0];
    const int fg = ft * 8 + f;
    float* orow = out + ((size_t)b * S + fg) * S;
    orow[t0]     = acc0 + bm2s;
    orow[t0 + 1] = acc1v + bm2s;
}

// ---------------------------------------------------------------------------
// Launcher: QKV ig_gemm is OUR 4th launch (ncu -s 5 lands on harness+2 -> us+4)
// ---------------------------------------------------------------------------
extern "C" void kernel_launch(void* const* d_in, const int* in_sizes, int n_in,
                              void* d_out, int out_size)
{
    const float* emb   = (const float*)d_in[0];
    const float* Wqkv  = (const float*)d_in[1];
    const float* bqkv  = (const float*)d_in[2];
    const float* Wo    = (const float*)d_in[3];
    const float* bo    = (const float*)d_in[4];
    const float* ln1_g = (const float*)d_in[5];
    const float* ln1_b = (const float*)d_in[6];
    const float* ln2_g = (const float*)d_in[7];
    const float* ln2_b = (const float*)d_in[8];
    const float* W1    = (const float*)d_in[9];
    const float* b1    = (const float*)d_in[10];
    const float* W2    = (const float*)d_in[11];
    const float* b2    = (const float*)d_in[12];
    const float* Wm1   = (const float*)d_in[13];
    const float* bm1   = (const float*)d_in[14];
    const float* Wm2   = (const float*)d_in[15];
    const float* bm2   = (const float*)d_in[16];
    float* out = (float*)d_out;

    float *x, *qkvb, *ao, *tmp, *hb, *fb, *tb;
    cudaGetSymbolAddress((void**)&x, g_x);
    cudaGetSymbolAddress((void**)&qkvb, g_qkv);
    cudaGetSymbolAddress((void**)&ao, g_ao);
    cudaGetSymbolAddress((void**)&tmp, g_tmp);
    cudaGetSymbolAddress((void**)&hb, g_h);
    cudaGetSymbolAddress((void**)&fb, g_f);
    cudaGetSymbolAddress((void**)&tb, g_t);

    int8_t *x1, *x2, *ao1, *ao2, *h1, *h2;
    int8_t *wq1, *wq2, *wo1, *wo2, *w11, *w12, *w21, *w22, *mf1, *mf2, *mt1, *mt2;
    float *sx, *sao, *sh, *swq, *swo, *sw1, *sw2, *smf, *smt;
    cudaGetSymbolAddress((void**)&x1, q_x1);   cudaGetSymbolAddress((void**)&x2, q_x2);
    cudaGetSymbolAddress((void**)&ao1, q_ao1); cudaGetSymbolAddress((void**)&ao2, q_ao2);
    cudaGetSymbolAddress((void**)&h1, q_h1);   cudaGetSymbolAddress((void**)&h2, q_h2);
    cudaGetSymbolAddress((void**)&wq1, q_wqkv1); cudaGetSymbolAddress((void**)&wq2, q_wqkv2);
    cudaGetSymbolAddress((void**)&wo1, q_wo1); cudaGetSymbolAddress((void**)&wo2, q_wo2);
    cudaGetSymbolAddress((void**)&w11, q_w11); cudaGetSymbolAddress((void**)&w12, q_w12);
    cudaGetSymbolAddress((void**)&w21, q_w21); cudaGetSymbolAddress((void**)&w22, q_w22);
    cudaGetSymbolAddress((void**)&mf1, q_wm1f1); cudaGetSymbolAddress((void**)&mf2, q_wm1f2);
    cudaGetSymbolAddress((void**)&mt1, q_wm1t1); cudaGetSymbolAddress((void**)&mt2, q_wm1t2);
    cudaGetSymbolAddress((void**)&sx, s_x);    cudaGetSymbolAddress((void**)&sao, s_ao);
    cudaGetSymbolAddress((void**)&sh, s_h);    cudaGetSymbolAddress((void**)&swq, s_wqkv);
    cudaGetSymbolAddress((void**)&swo, s_wo);  cudaGetSymbolAddress((void**)&sw1, s_w1);
    cudaGetSymbolAddress((void**)&sw2, s_w2);  cudaGetSymbolAddress((void**)&smf, s_wm1f);
    cudaGetSymbolAddress((void**)&smt, s_wm1t);

    cudaFuncSetAttribute(ig_gemm<0>, cudaFuncAttributeMaxDynamicSharedMemorySize, IG_SMEM);
    cudaFuncSetAttribute(ig_gemm<1>, cudaFuncAttributeMaxDynamicSharedMemorySize, IG_SMEM);
    cudaFuncSetAttribute(attn_kernel, cudaFuncAttributeMaxDynamicSharedMemorySize, ATT_SMEM);

    const dim3 gQKV(3 * D / 64, M_TOT / 128);   // (24, 32)
    const dim3 gD  (D / 64,     M_TOT / 128);   // (8, 32)
    const dim3 gFF (FF / 64,    M_TOT / 128);   // (16, 32)

    // Launch order: our #4 is the layer-0 QKV GEMM (ncu capture target).
    quant_rows<512><<<LAYERS * 3 * D, 128>>>(Wqkv, D, wq1, wq2, swq, nullptr);   // 1
    quant_rows<512><<<M_TOT, 128>>>(emb, D, x1, x2, sx, x);                      // 2 (also emb->g_x)
    quant_rows<512><<<LAYERS * D, 128>>>(Wo, D, wo1, wo2, swo, nullptr);         // 3

    for (int l = 0; l < LAYERS; l++) {
        ig_gemm<0><<<gQKV, 256, IG_SMEM>>>(                                       // 4 on l=0
            x1, x2, sx, D,
            wq1 + (size_t)l * 3 * D * D, wq2 + (size_t)l * 3 * D * D,
            swq + (size_t)l * 3 * D, D,
            bqkv + (size_t)l * 3 * D, qkvb, 3 * D, D);
        attn_kernel<<<B * H, 256, ATT_SMEM>>>(qkvb, ao);
        if (l == 0) {
            quant_rows<512><<<LAYERS * FF, 128>>>(W1, D, w11, w12, sw1, nullptr);
            quant_rows<1024><<<LAYERS * D, 128>>>(W2, FF, w21, w22, sw2, nullptr);
        }
        quant_rows<512><<<M_TOT, 128>>>(ao, D, ao1, ao2, sao, nullptr);
        ig_gemm<0><<<gD, 256, IG_SMEM>>>(
            ao1, ao2, sao, D,
            wo1 + (size_t)l * D * D, wo2 + (size_t)l * D * D,
            swo + (size_t)l * D, D,
            bo + (size_t)l * D, tmp, D, D);
        add_ln_kernel<<<M_TOT, 128>>>(x, tmp, ln1_g + (size_t)l * D,
                                      ln1_b + (size_t)l * D, x1, x2, sx);
        ig_gemm<1><<<gFF, 256, IG_SMEM>>>(
            x1, x2, sx, D,
            w11 + (size_t)l * FF * D, w12 + (size_t)l * FF * D,
            sw1 + (size_t)l * FF, D,
            b1 + (size_t)l * FF, hb, FF, D);
        quant_rows<1024><<<M_TOT, 128>>>(hb, FF, h1, h2, sh, nullptr);
        ig_gemm<0><<<gD, 256, IG_SMEM>>>(
            h1, h2, sh, FF,
            w21 + (size_t)l * D * FF, w22 + (size_t)l * D * FF,
            sw2 + (size_t)l * D, FF,
            b2 + (size_t)l * D, tmp, D, FF);
        add_ln_kernel<<<M_TOT, 128>>>(x, tmp, ln2_g + (size_t)l * D,
                                      ln2_b + (size_t)l * D, x1, x2, sx);
    }

    quant_wm1<<<2 * FF, 128>>>(Wm1, mf1, mf2, smf, mt1, mt2, smt);
    ig_gemm<0><<<gFF, 256, IG_SMEM>>>(
        x1, x2, sx, D, mf1, mf2, smf, D, nullptr, fb, FF, D);
    ig_gemm<0><<<gFF, 256, IG_SMEM>>>(
        x1, x2, sx, D, mt1, mt2, smt, D, nullptr, tb, FF, D);
    pairwise_kernel<<<B * 8, 256>>>(fb, tb, bm1, Wm2, bm2, out);
}

// round 17
// speedup vs baseline: 1.0401x; 1.0077x over previous
#include <cuda_runtime.h>
#include <cuda_bf16.h>
#include <math.h>
#include <stdint.h>

#define LAYERS 4
#define D 512
#define H 8
#define HD 64
#define FF 1024
#define B 64
#define S 64
#define M_TOT (B * S)
#define EPS 1e-5f

// ---------------------------------------------------------------------------
// Scratch buffers
// ---------------------------------------------------------------------------
__device__ float g_x[M_TOT * D];
__device__ float g_qkv[M_TOT * 3 * D];
__device__ float g_ao[M_TOT * D];
__device__ float g_tmp[M_TOT * D];
__device__ float g_h[M_TOT * FF];
__device__ float g_ft[M_TOT * 2 * FF];      // head f|t combined (32 MB)

__device__ int8_t q_x1[M_TOT * D],  q_x2[M_TOT * D];
__device__ int8_t q_ao1[M_TOT * D], q_ao2[M_TOT * D];
__device__ int8_t q_h1[M_TOT * FF], q_h2[M_TOT * FF];
__device__ int8_t q_wqkv1[LAYERS * 3 * D * D], q_wqkv2[LAYERS * 3 * D * D];
__device__ int8_t q_wo1[LAYERS * D * D],       q_wo2[LAYERS * D * D];
__device__ int8_t q_w11[LAYERS * FF * D],      q_w12[LAYERS * FF * D];
__device__ int8_t q_w21[LAYERS * D * FF],      q_w22[LAYERS * D * FF];
__device__ int8_t q_wm1c1[2 * FF * D], q_wm1c2[2 * FF * D];   // f rows 0..1023, t rows 1024..2047

__device__ float s_x[M_TOT], s_ao[M_TOT], s_h[M_TOT];
__device__ float s_wqkv[LAYERS * 3 * D], s_wo[LAYERS * D];
__device__ float s_w1[LAYERS * FF], s_w2[LAYERS * D];
__device__ float s_wm1c[2 * FF];

// ---------------------------------------------------------------------------
// Helpers
// ---------------------------------------------------------------------------
__device__ __forceinline__ float gelu_exact(float x) {
    return 0.5f * x * (1.0f + erff(x * 0.70710678118654752f));
}
__device__ __forceinline__ float tanh_fast(float x) {
    float y;
    asm("tanh.approx.f32 %0, %1;" : "=f"(y) : "f"(x));
    return y;
}
__device__ __forceinline__ float gelu_fast(float x) {
    float u = x * x;
    float z = x * fmaf(0.0356774081f, u, 0.7978845608f);
    float th = tanh_fast(z);
    float hx = 0.5f * x;
    return fmaf(hx, th, hx);
}
__device__ __forceinline__ uint32_t smem_u32(const void* p) {
    uint32_t a;
    asm("{ .reg .u64 t; cvta.to.shared.u64 t, %1; cvt.u32.u64 %0, t; }"
        : "=r"(a) : "l"(p));
    return a;
}
__device__ __forceinline__ void ldmx4(uint32_t* r, uint32_t addr) {
    asm volatile("ldmatrix.sync.aligned.m8n8.x4.shared.b16 {%0,%1,%2,%3}, [%4];"
                 : "=r"(r[0]), "=r"(r[1]), "=r"(r[2]), "=r"(r[3]) : "r"(addr));
}
__device__ __forceinline__ void imma(int* d, const uint32_t* a, const uint32_t* b) {
    asm volatile(
        "mma.sync.aligned.m16n8k32.row.col.s32.s8.s8.s32 "
        "{%0,%1,%2,%3}, {%4,%5,%6,%7}, {%8,%9}, {%0,%1,%2,%3};"
        : "+r"(d[0]), "+r"(d[1]), "+r"(d[2]), "+r"(d[3])
        : "r"(a[0]), "r"(a[1]), "r"(a[2]), "r"(a[3]), "r"(b[0]), "r"(b[1]));
}
__device__ __forceinline__ void cp16(uint32_t saddr, const void* gptr) {
    asm volatile("cp.async.cg.shared.global [%0], [%1], 16;"
                 :: "r"(saddr), "l"(gptr));
}
__device__ __forceinline__ void cp_commit() {
    asm volatile("cp.async.commit_group;");
}
template <int N>
__device__ __forceinline__ void cp_wait() {
    asm volatile("cp.async.wait_group %0;" :: "n"(N));
}

// ---------------------------------------------------------------------------
// Block-level (128 threads) two-level int8 row quantization
// ---------------------------------------------------------------------------
template <int LEN>
__device__ __forceinline__ void quant_row_block(
    const float* __restrict__ src, int8_t* __restrict__ q1row,
    int8_t* __restrict__ q2row, float* __restrict__ scale_slot,
    float* __restrict__ cpy)
{
    const int tid = threadIdx.x;
    const int warp = tid >> 5, lane = tid & 31;
    float4 v[LEN / 512];
    float m = 0.0f;
#pragma unroll
    for (int p = 0; p < LEN / 512; p++) {
        v[p] = *((const float4*)src + p * 128 + tid);
        m = fmaxf(m, fmaxf(fmaxf(fabsf(v[p].x), fabsf(v[p].y)),
                           fmaxf(fabsf(v[p].z), fabsf(v[p].w))));
    }
#pragma unroll
    for (int o = 16; o > 0; o >>= 1) m = fmaxf(m, __shfl_xor_sync(~0u, m, o));
    __shared__ float sm[4];
    if (lane == 0) sm[warp] = m;
    __syncthreads();
    m = fmaxf(fmaxf(sm[0], sm[1]), fmaxf(sm[2], sm[3]));
    m = fmaxf(m, 1e-30f);

    const float s1 = m * (1.0f / 127.0f);
    const float i1 = 127.0f / m;
    const float i2 = 254.0f / s1;
    if (tid == 0) *scale_slot = s1;

    int* q1p = (int*)q1row;
    int* q2p = (int*)q2row;
#pragma unroll
    for (int p = 0; p < LEN / 512; p++) {
        float xs[4] = {v[p].x, v[p].y, v[p].z, v[p].w};
        int pk1 = 0, pk2 = 0;
#pragma unroll
        for (int e = 0; e < 4; e++) {
            int a = __float2int_rn(xs[e] * i1);
            float r = xs[e] - s1 * (float)a;
            int b2 = __float2int_rn(r * i2);
            b2 = max(-127, min(127, b2));
            pk1 |= (a & 255) << (8 * e);
            pk2 |= (b2 & 255) << (8 * e);
        }
        q1p[p * 128 + tid] = pk1;
        q2p[p * 128 + tid] = pk2;
        if (cpy) *((float4*)cpy + p * 128 + tid) = v[p];
    }
}

template <int LEN>
__global__ void __launch_bounds__(128) quant_rows(
    const float* __restrict__ src, int lds,
    int8_t* __restrict__ q1, int8_t* __restrict__ q2,
    float* __restrict__ scale, float* __restrict__ cpy)
{
    const int r = blockIdx.x;
    quant_row_block<LEN>(src + (size_t)r * lds,
                         q1 + (size_t)r * LEN, q2 + (size_t)r * LEN,
                         scale + r, cpy ? cpy + (size_t)r * LEN : nullptr);
}

// All transformer weights in one launch (block-range dispatch).
// 0..6143: Wqkv | 6144..8191: Wo | 8192..12287: W1 | 12288..14335: W2
#define NQW (LAYERS * 3 * D + LAYERS * D + LAYERS * FF + LAYERS * D)   // 14336

__global__ void __launch_bounds__(128) quant_weights(
    const float* __restrict__ Wqkv, const float* __restrict__ Wo,
    const float* __restrict__ W1, const float* __restrict__ W2)
{
    int r = blockIdx.x;
    if (r < LAYERS * 3 * D) {
        quant_row_block<512>(Wqkv + (size_t)r * D,
                             q_wqkv1 + (size_t)r * D, q_wqkv2 + (size_t)r * D,
                             s_wqkv + r, nullptr);
    } else if ((r -= LAYERS * 3 * D) < LAYERS * D) {
        quant_row_block<512>(Wo + (size_t)r * D,
                             q_wo1 + (size_t)r * D, q_wo2 + (size_t)r * D,
                             s_wo + r, nullptr);
    } else if ((r -= LAYERS * D) < LAYERS * FF) {
        quant_row_block<512>(W1 + (size_t)r * D,
                             q_w11 + (size_t)r * D, q_w12 + (size_t)r * D,
                             s_w1 + r, nullptr);
    } else {
        r -= LAYERS * FF;
        quant_row_block<1024>(W2 + (size_t)r * FF,
                              q_w21 + (size_t)r * FF, q_w22 + (size_t)r * FF,
                              s_w2 + r, nullptr);
    }
}

// Combined wm1: row r<FF -> f half (Wm1 row r, cols 0..511);
// row r>=FF -> t half (Wm1 row r-FF, cols 512..1023). Output contiguous.
__global__ void __launch_bounds__(128) quant_wm1c(const float* __restrict__ Wm1)
{
    const int r = blockIdx.x;
    const float* src = (r < FF) ? (Wm1 + (size_t)r * 2 * D)
                                : (Wm1 + (size_t)(r - FF) * 2 * D + D);
    quant_row_block<512>(src, q_wm1c1 + (size_t)r * D, q_wm1c2 + (size_t)r * D,
                         s_wm1c + r, nullptr);
}

// ---------------------------------------------------------------------------
// int8 split tensor-core GEMM (IMMA m16n8k32), 128x64 tile,
// K-chunks of 128 B, 2-stage cp.async pipeline, ONE sync per chunk,
// 2 CTAs/SM.  (Best validated config, 39.2us QKV.)
// ---------------------------------------------------------------------------
#define AROW 144
#define A_TILE_B (128 * AROW)
#define B_TILE_B (64 * AROW)
#define ST_A1 0
#define ST_A2 A_TILE_B
#define ST_B1 (2 * A_TILE_B)
#define ST_B2 (2 * A_TILE_B + B_TILE_B)
#define STAGE_B (2 * A_TILE_B + 2 * B_TILE_B)
#define IG_SMEM (2 * STAGE_B)

template <int MODE>
__global__ void __launch_bounds__(256, 2) ig_gemm(
    const int8_t* __restrict__ Aq1, const int8_t* __restrict__ Aq2,
    const float* __restrict__ sA, int lda,
    const int8_t* __restrict__ Bq1, const int8_t* __restrict__ Bq2,
    const float* __restrict__ sB, int ldb,
    const float* __restrict__ bias,
    float* __restrict__ C, int ldc, int K)
{
    extern __shared__ char smem[];
    const uint32_t sb = smem_u32(smem);
    const int tid = threadIdx.x;
    const int wid = tid >> 5, lane = tid & 31;
    const int wm = wid >> 1;
    const int wn = wid & 1;
    const int brow = blockIdx.y * 128;
    const int bcol = blockIdx.x * 64;

    int rowgA[4], segA[4], smoffA[4];
#pragma unroll
    for (int t = 0; t < 4; t++) {
        int sid = tid + (t << 8);
        rowgA[t] = sid >> 3;
        segA[t] = (sid & 7) * 16;
        smoffA[t] = rowgA[t] * AROW + segA[t];
    }
    int rowgB[2], segB[2], smoffB[2];
#pragma unroll
    for (int t = 0; t < 2; t++) {
        int sid = tid + (t << 8);
        rowgB[t] = sid >> 3;
        segB[t] = (sid & 7) * 16;
        smoffB[t] = rowgB[t] * AROW + segB[t];
    }

    const int8_t* pA1 = Aq1 + (size_t)brow * lda;
    const int8_t* pA2 = Aq2 + (size_t)brow * lda;
    const int8_t* pB1 = Bq1 + (size_t)bcol * ldb;
    const int8_t* pB2 = Bq2 + (size_t)bcol * ldb;

    const uint32_t a_loff = (uint32_t)((wm * 32 + (lane & 15)) * AROW + (lane >> 4) * 16);
    const uint32_t b_loff = (uint32_t)((wn * 32 + (lane & 7) + ((lane >> 4) << 3)) * AROW
                                       + ((lane >> 3) & 1) * 16);

    int acc1[2][4][4];
    int accx[2][4][4];
#pragma unroll
    for (int i = 0; i < 2; i++)
#pragma unroll
        for (int j = 0; j < 4; j++)
#pragma unroll
            for (int e = 0; e < 4; e++) { acc1[i][j][e] = 0; accx[i][j][e] = 0; }

    const int NC = K >> 7;

#define IG_ISSUE(snb, kc) do {                                           \
    const uint32_t _s = (snb);                                           \
    _Pragma("unroll")                                                    \
    for (int t = 0; t < 4; t++) {                                        \
        const int go = rowgA[t] * lda + segA[t] + (kc);                  \
        cp16(_s + ST_A1 + smoffA[t], pA1 + go);                          \
        cp16(_s + ST_A2 + smoffA[t], pA2 + go);                          \
    }                                                                    \
    _Pragma("unroll")                                                    \
    for (int t = 0; t < 2; t++) {                                        \
        const int gob = rowgB[t] * ldb + segB[t] + (kc);                 \
        cp16(_s + ST_B1 + smoffB[t], pB1 + gob);                         \
        cp16(_s + ST_B2 + smoffB[t], pB2 + gob);                         \
    }                                                                    \
    cp_commit();                                                         \
} while (0)

    IG_ISSUE(sb, 0);

    for (int c = 0; c < NC; c++) {
        cp_wait<0>();
        __syncthreads();
        if (c + 1 < NC) {
            IG_ISSUE(sb + ((c + 1) & 1) * STAGE_B, (c + 1) << 7);
        }

        const uint32_t base = sb + (c & 1) * STAGE_B;
#pragma unroll
        for (int kk = 0; kk < 4; kk++) {
            const uint32_t kb = kk * 32;
            uint32_t b1r[8], b2r[8];
#pragma unroll
            for (int j = 0; j < 2; j++) {
                ldmx4(&b1r[j * 4], base + ST_B1 + j * (16 * AROW) + kb + b_loff);
                ldmx4(&b2r[j * 4], base + ST_B2 + j * (16 * AROW) + kb + b_loff);
            }
#pragma unroll
            for (int i = 0; i < 2; i++) {
                uint32_t a1[4], a2[4];
                ldmx4(a1, base + ST_A1 + i * (16 * AROW) + kb + a_loff);
                ldmx4(a2, base + ST_A2 + i * (16 * AROW) + kb + a_loff);
#pragma unroll
                for (int jn = 0; jn < 4; jn++) {
                    const uint32_t* bp1 = &b1r[(jn >> 1) * 4 + (jn & 1) * 2];
                    const uint32_t* bp2 = &b2r[(jn >> 1) * 4 + (jn & 1) * 2];
                    imma(acc1[i][jn], a1, bp1);
                    imma(accx[i][jn], a1, bp2);
                    imma(accx[i][jn], a2, bp1);
                }
            }
        }
    }
#undef IG_ISSUE

    const int lm = lane >> 2;
    const int ln = (lane & 3) * 2;
    const float inv254 = 1.0f / 254.0f;
#pragma unroll
    for (int i = 0; i < 2; i++) {
        const int r0 = brow + wm * 32 + i * 16 + lm;
        const float sa0 = sA[r0];
        const float sa1 = sA[r0 + 8];
#pragma unroll
        for (int jn = 0; jn < 4; jn++) {
            const int n = bcol + wn * 32 + jn * 8 + ln;
            const float sb0 = sB[n], sb1 = sB[n + 1];
            const float b0 = bias ? bias[n] : 0.0f;
            const float b1 = bias ? bias[n + 1] : 0.0f;
            float d0 = sa0 * sb0 * ((float)acc1[i][jn][0] + (float)accx[i][jn][0] * inv254) + b0;
            float d1 = sa0 * sb1 * ((float)acc1[i][jn][1] + (float)accx[i][jn][1] * inv254) + b1;
            float d2 = sa1 * sb0 * ((float)acc1[i][jn][2] + (float)accx[i][jn][2] * inv254) + b0;
            float d3 = sa1 * sb1 * ((float)acc1[i][jn][3] + (float)accx[i][jn][3] * inv254) + b1;
            if (MODE == 1) {
                d0 = gelu_exact(d0); d1 = gelu_exact(d1);
                d2 = gelu_exact(d2); d3 = gelu_exact(d3);
            }
            *(float2*)(C + (size_t)r0 * ldc + n) = make_float2(d0, d1);
            *(float2*)(C + (size_t)(r0 + 8) * ldc + n) = make_float2(d2, d3);
        }
    }
}

// ---------------------------------------------------------------------------
// Attention: one block per (b,h). Vectorized float4 inner loops.
// ---------------------------------------------------------------------------
#define QS 68
#define ATT_SMEM ((64 * QS + 2 * 64 * 64) * 4)

__global__ void __launch_bounds__(256) attn_kernel(
    const float* __restrict__ qkv, float* __restrict__ out)
{
    extern __shared__ float asm_[];
    float* Qs = asm_;
    float* Kt = asm_ + 64 * QS;
    float* Vs = Kt + 64 * 64;

    const int bh = blockIdx.x;
    const int b = bh >> 3;
    const int h = bh & 7;
    const int tid = threadIdx.x;
    const float* base = qkv + (size_t)b * S * (3 * D) + h * HD;

    {
        const int r = tid >> 2;
        const int c0 = (tid & 3) * 16;
#pragma unroll
        for (int i = 0; i < 4; i++) {
            int c = c0 + i * 4;
            float4 qv = *(const float4*)(base + (size_t)r * (3 * D) + c);
            float4 kv = *(const float4*)(base + (size_t)r * (3 * D) + D + c);
            float4 vv = *(const float4*)(base + (size_t)r * (3 * D) + 2 * D + c);
            *(float4*)(&Qs[r * QS + c]) = qv;
            *(float4*)(&Vs[r * 64 + c]) = vv;
            Kt[(c + 0) * 64 + r] = kv.x; Kt[(c + 1) * 64 + r] = kv.y;
            Kt[(c + 2) * 64 + r] = kv.z; Kt[(c + 3) * 64 + r] = kv.w;
        }
    }
    __syncthreads();

    const int i = tid >> 2;
    const int j0 = (tid & 3) * 16;

    float sc[16];
#pragma unroll
    for (int e = 0; e < 16; e++) sc[e] = 0.0f;
#pragma unroll 8
    for (int d = 0; d < 64; d++) {
        float qv = Qs[i * QS + d];
        const float* kr = &Kt[d * 64 + j0];
        float4 k0 = *(const float4*)(kr);
        float4 k1 = *(const float4*)(kr + 4);
        float4 k2 = *(const float4*)(kr + 8);
        float4 k3 = *(const float4*)(kr + 12);
        sc[0] = fmaf(qv, k0.x, sc[0]);  sc[1] = fmaf(qv, k0.y, sc[1]);
        sc[2] = fmaf(qv, k0.z, sc[2]);  sc[3] = fmaf(qv, k0.w, sc[3]);
        sc[4] = fmaf(qv, k1.x, sc[4]);  sc[5] = fmaf(qv, k1.y, sc[5]);
        sc[6] = fmaf(qv, k1.z, sc[6]);  sc[7] = fmaf(qv, k1.w, sc[7]);
        sc[8] = fmaf(qv, k2.x, sc[8]);  sc[9] = fmaf(qv, k2.y, sc[9]);
        sc[10] = fmaf(qv, k2.z, sc[10]); sc[11] = fmaf(qv, k2.w, sc[11]);
        sc[12] = fmaf(qv, k3.x, sc[12]); sc[13] = fmaf(qv, k3.y, sc[13]);
        sc[14] = fmaf(qv, k3.z, sc[14]); sc[15] = fmaf(qv, k3.w, sc[15]);
    }
    __syncthreads();

    float* P = Qs;
#pragma unroll
    for (int e = 0; e < 4; e++) {
        float4 v = make_float4(sc[e * 4] * 0.125f, sc[e * 4 + 1] * 0.125f,
                               sc[e * 4 + 2] * 0.125f, sc[e * 4 + 3] * 0.125f);
        *(float4*)(&P[i * QS + j0 + e * 4]) = v;
    }
    __syncthreads();

    const int warp = tid >> 5, lane = tid & 31;
#pragma unroll
    for (int rr = 0; rr < 8; rr++) {
        int r = warp + rr * 8;
        float v0 = P[r * QS + lane], v1 = P[r * QS + lane + 32];
        float mx = fmaxf(v0, v1);
#pragma unroll
        for (int o = 16; o > 0; o >>= 1) mx = fmaxf(mx, __shfl_xor_sync(~0u, mx, o));
        float e0 = __expf(v0 - mx), e1 = __expf(v1 - mx);
        float ssum = e0 + e1;
#pragma unroll
        for (int o = 16; o > 0; o >>= 1) ssum += __shfl_xor_sync(~0u, ssum, o);
        float inv = 1.0f / ssum;
        P[r * QS + lane] = e0 * inv;
        P[r * QS + lane + 32] = e1 * inv;
    }
    __syncthreads();

    float o[16];
#pragma unroll
    for (int e = 0; e < 16; e++) o[e] = 0.0f;
#pragma unroll 8
    for (int j = 0; j < 64; j++) {
        float pv = P[i * QS + j];
        const float* vr = &Vs[j * 64 + j0];
        float4 v0 = *(const float4*)(vr);
        float4 v1 = *(const float4*)(vr + 4);
        float4 v2 = *(const float4*)(vr + 8);
        float4 v3 = *(const float4*)(vr + 12);
        o[0] = fmaf(pv, v0.x, o[0]);   o[1] = fmaf(pv, v0.y, o[1]);
        o[2] = fmaf(pv, v0.z, o[2]);   o[3] = fmaf(pv, v0.w, o[3]);
        o[4] = fmaf(pv, v1.x, o[4]);   o[5] = fmaf(pv, v1.y, o[5]);
        o[6] = fmaf(pv, v1.z, o[6]);   o[7] = fmaf(pv, v1.w, o[7]);
        o[8] = fmaf(pv, v2.x, o[8]);   o[9] = fmaf(pv, v2.y, o[9]);
        o[10] = fmaf(pv, v2.z, o[10]); o[11] = fmaf(pv, v2.w, o[11]);
        o[12] = fmaf(pv, v3.x, o[12]); o[13] = fmaf(pv, v3.y, o[13]);
        o[14] = fmaf(pv, v3.z, o[14]); o[15] = fmaf(pv, v3.w, o[15]);
    }
    float* orow = out + (size_t)(b * S + i) * D + h * HD + j0;
#pragma unroll
    for (int e = 0; e < 4; e++)
        *(float4*)(orow + e * 4) = make_float4(o[e * 4], o[e * 4 + 1],
                                               o[e * 4 + 2], o[e * 4 + 3]);
}

// ---------------------------------------------------------------------------
// Fused residual add + LayerNorm + quant
// ---------------------------------------------------------------------------
__global__ void __launch_bounds__(128) add_ln_kernel(
    float* __restrict__ x, const float* __restrict__ y,
    const float* __restrict__ g, const float* __restrict__ bta,
    int8_t* __restrict__ q1, int8_t* __restrict__ q2,
    float* __restrict__ scale)
{
    const int row = blockIdx.x;
    const int tid = threadIdx.x;
    const int warp = tid >> 5, lane = tid & 31;

    float4 xv = *(const float4*)(x + (size_t)row * D + tid * 4);
    float4 yv = *(const float4*)(y + (size_t)row * D + tid * 4);
    float s0 = xv.x + yv.x, s1v = xv.y + yv.y, s2 = xv.z + yv.z, s3 = xv.w + yv.w;

    float sum = s0 + s1v + s2 + s3;
    float sq = fmaf(s0, s0, fmaf(s1v, s1v, fmaf(s2, s2, s3 * s3)));
#pragma unroll
    for (int o = 16; o > 0; o >>= 1) {
        sum += __shfl_xor_sync(~0u, sum, o);
        sq  += __shfl_xor_sync(~0u, sq, o);
    }
    __shared__ float sh[8];
    __shared__ float smax[4];
    if (lane == 0) { sh[warp] = sum; sh[4 + warp] = sq; }
    __syncthreads();
    sum = sh[0] + sh[1] + sh[2] + sh[3];
    sq  = sh[4] + sh[5] + sh[6] + sh[7];

    const float mu = sum * (1.0f / D);
    const float var = sq * (1.0f / D) - mu * mu;
    const float inv = rsqrtf(var + EPS);

    float4 gv = *(const float4*)(g + tid * 4);
    float4 bv = *(const float4*)(bta + tid * 4);
    float o0 = (s0 - mu) * inv * gv.x + bv.x;
    float o1 = (s1v - mu) * inv * gv.y + bv.y;
    float o2 = (s2 - mu) * inv * gv.z + bv.z;
    float o3 = (s3 - mu) * inv * gv.w + bv.w;
    *(float4*)(x + (size_t)row * D + tid * 4) = make_float4(o0, o1, o2, o3);

    float m = fmaxf(fmaxf(fabsf(o0), fabsf(o1)), fmaxf(fabsf(o2), fabsf(o3)));
#pragma unroll
    for (int o = 16; o > 0; o >>= 1) m = fmaxf(m, __shfl_xor_sync(~0u, m, o));
    if (lane == 0) smax[warp] = m;
    __syncthreads();
    m = fmaxf(fmaxf(smax[0], smax[1]), fmaxf(smax[2], smax[3]));
    m = fmaxf(m, 1e-30f);

    const float s1q = m * (1.0f / 127.0f);
    const float i1 = 127.0f / m;
    const float i2 = 254.0f / s1q;
    if (tid == 0) scale[row] = s1q;

    float xs[4] = {o0, o1, o2, o3};
    int pk1 = 0, pk2 = 0;
#pragma unroll
    for (int e = 0; e < 4; e++) {
        int a = __float2int_rn(xs[e] * i1);
        float rr = xs[e] - s1q * (float)a;
        int b2 = __float2int_rn(rr * i2);
        b2 = max(-127, min(127, b2));
        pk1 |= (a & 255) << (8 * e);
        pk2 |= (b2 & 255) << (8 * e);
    }
    ((int*)(q1 + (size_t)row * D))[tid] = pk1;
    ((int*)(q2 + (size_t)row * D))[tid] = pk2;
}

// ---------------------------------------------------------------------------
// Pairwise policy head (tanh-gelu), float4-vectorized, stride-param F/T.
// ---------------------------------------------------------------------------
#define PCH 128
#define TSTR 132

__global__ void __launch_bounds__(256) pairwise_kernel(
    const float* __restrict__ F, const float* __restrict__ T, int lds,
    const float* __restrict__ bm1, const float* __restrict__ wm2,
    const float* __restrict__ bm2v, float* __restrict__ out)
{
    const int b = blockIdx.x >> 3;
    const int ft = blockIdx.x & 7;

    __shared__ __align__(16) float Fs[8 * TSTR];
    __shared__ __align__(16) float Ts[64 * TSTR];
    __shared__ __align__(16) float ws[PCH];

    const int tid = threadIdx.x;
    const int f = tid & 7;
    const int t0 = (tid >> 3) * 2;

    float acc0 = 0.0f, acc1v = 0.0f;
    const float* Fbase = F + ((size_t)b * S + ft * 8) * lds;
    const float* Tbase = T + (size_t)b * S * lds;

    for (int c = 0; c < FF; c += PCH) {
        {
            int fr = tid >> 5, cc = (tid & 31) * 4;
            float4 fv = *(const float4*)(Fbase + (size_t)fr * lds + c + cc);
            *(float4*)(&Fs[fr * TSTR + cc]) = fv;
        }
        if (tid < 32) *(float4*)(&ws[tid * 4]) = *(const float4*)(wm2 + c + tid * 4);
        {
            int tr = tid >> 2, tcc0 = (tid & 3) * 32;
#pragma unroll
            for (int i = 0; i < 8; i++) {
                int cc = tcc0 + i * 4;
                float4 tv = *(const float4*)(Tbase + (size_t)tr * lds + c + cc);
                float4 bb = *(const float4*)(bm1 + c + cc);
                float4 sv = make_float4(tv.x + bb.x, tv.y + bb.y,
                                        tv.z + bb.z, tv.w + bb.w);
                *(float4*)(&Ts[tr * TSTR + cc]) = sv;
            }
        }
        __syncthreads();

        const float* fr = &Fs[f * TSTR];
        const float* ta = &Ts[t0 * TSTR];
        const float* tb = &Ts[(t0 + 1) * TSTR];
#pragma unroll 8
        for (int hh = 0; hh < PCH; hh += 4) {
            float4 w4 = *(const float4*)(&ws[hh]);
            float4 f4 = *(const float4*)(fr + hh);
            float4 a4 = *(const float4*)(ta + hh);
            float4 b4 = *(const float4*)(tb + hh);
            acc0  = fmaf(gelu_fast(f4.x + a4.x), w4.x, acc0);
            acc0  = fmaf(gelu_fast(f4.y + a4.y), w4.y, acc0);
            acc0  = fmaf(gelu_fast(f4.z + a4.z), w4.z, acc0);
            acc0  = fmaf(gelu_fast(f4.w + a4.w), w4.w, acc0);
            acc1v = fmaf(gelu_fast(f4.x + b4.x), w4.x, acc1v);
            acc1v = fmaf(gelu_fast(f4.y + b4.y), w4.y, acc1v);
            acc1v = fmaf(gelu_fast(f4.z + b4.z), w4.z, acc1v);
            acc1v = fmaf(gelu_fast(f4.w + b4.w), w4.w, acc1v);
        }
        __syncthreads();
    }

    const float bm2s = bm2v[0];
    const int fg = ft * 8 + f;
    float* orow = out + ((size_t)b * S + fg) * S;
    orow[t0]     = acc0 + bm2s;
    orow[t0 + 1] = acc1v + bm2s;
}

// ---------------------------------------------------------------------------
// Launcher: QKV ig_gemm is OUR 4th launch (ncu -s 5 lands on harness+2 -> us+4)
// ---------------------------------------------------------------------------
extern "C" void kernel_launch(void* const* d_in, const int* in_sizes, int n_in,
                              void* d_out, int out_size)
{
    const float* emb   = (const float*)d_in[0];
    const float* Wqkv  = (const float*)d_in[1];
    const float* bqkv  = (const float*)d_in[2];
    const float* Wo    = (const float*)d_in[3];
    const float* bo    = (const float*)d_in[4];
    const float* ln1_g = (const float*)d_in[5];
    const float* ln1_b = (const float*)d_in[6];
    const float* ln2_g = (const float*)d_in[7];
    const float* ln2_b = (const float*)d_in[8];
    const float* W1    = (const float*)d_in[9];
    const float* b1    = (const float*)d_in[10];
    const float* W2    = (const float*)d_in[11];
    const float* b2    = (const float*)d_in[12];
    const float* Wm1   = (const float*)d_in[13];
    const float* bm1   = (const float*)d_in[14];
    const float* Wm2   = (const float*)d_in[15];
    const float* bm2   = (const float*)d_in[16];
    float* out = (float*)d_out;

    float *x, *qkvb, *ao, *tmp, *hb, *ftb;
    cudaGetSymbolAddress((void**)&x, g_x);
    cudaGetSymbolAddress((void**)&qkvb, g_qkv);
    cudaGetSymbolAddress((void**)&ao, g_ao);
    cudaGetSymbolAddress((void**)&tmp, g_tmp);
    cudaGetSymbolAddress((void**)&hb, g_h);
    cudaGetSymbolAddress((void**)&ftb, g_ft);

    int8_t *x1, *x2, *ao1, *ao2, *h1, *h2;
    int8_t *wq1, *wq2, *wo1, *wo2, *w11, *w12, *w21, *w22, *mc1, *mc2;
    float *sx, *sao, *sh, *swq, *swo, *sw1, *sw2, *smc;
    cudaGetSymbolAddress((void**)&x1, q_x1);   cudaGetSymbolAddress((void**)&x2, q_x2);
    cudaGetSymbolAddress((void**)&ao1, q_ao1); cudaGetSymbolAddress((void**)&ao2, q_ao2);
    cudaGetSymbolAddress((void**)&h1, q_h1);   cudaGetSymbolAddress((void**)&h2, q_h2);
    cudaGetSymbolAddress((void**)&wq1, q_wqkv1); cudaGetSymbolAddress((void**)&wq2, q_wqkv2);
    cudaGetSymbolAddress((void**)&wo1, q_wo1); cudaGetSymbolAddress((void**)&wo2, q_wo2);
    cudaGetSymbolAddress((void**)&w11, q_w11); cudaGetSymbolAddress((void**)&w12, q_w12);
    cudaGetSymbolAddress((void**)&w21, q_w21); cudaGetSymbolAddress((void**)&w22, q_w22);
    cudaGetSymbolAddress((void**)&mc1, q_wm1c1); cudaGetSymbolAddress((void**)&mc2, q_wm1c2);
    cudaGetSymbolAddress((void**)&sx, s_x);    cudaGetSymbolAddress((void**)&sao, s_ao);
    cudaGetSymbolAddress((void**)&sh, s_h);    cudaGetSymbolAddress((void**)&swq, s_wqkv);
    cudaGetSymbolAddress((void**)&swo, s_wo);  cudaGetSymbolAddress((void**)&sw1, s_w1);
    cudaGetSymbolAddress((void**)&sw2, s_w2);  cudaGetSymbolAddress((void**)&smc, s_wm1c);

    cudaFuncSetAttribute(ig_gemm<0>, cudaFuncAttributeMaxDynamicSharedMemorySize, IG_SMEM);
    cudaFuncSetAttribute(ig_gemm<1>, cudaFuncAttributeMaxDynamicSharedMemorySize, IG_SMEM);
    cudaFuncSetAttribute(attn_kernel, cudaFuncAttributeMaxDynamicSharedMemorySize, ATT_SMEM);

    const dim3 gQKV(3 * D / 64, M_TOT / 128);   // (24, 32)
    const dim3 gD  (D / 64,     M_TOT / 128);   // (8, 32)
    const dim3 gFF (FF / 64,    M_TOT / 128);   // (16, 32)
    const dim3 gHD (2 * FF / 64, M_TOT / 128);  // (32, 32) head combined

    // Launch order: our #4 is the layer-0 QKV GEMM (ncu capture target).
    quant_weights<<<NQW, 128>>>(Wqkv, Wo, W1, W2);                     // 1
    quant_rows<512><<<M_TOT, 128>>>(emb, D, x1, x2, sx, x);            // 2 (+emb->g_x)
    quant_wm1c<<<2 * FF, 128>>>(Wm1);                                  // 3

    for (int l = 0; l < LAYERS; l++) {
        ig_gemm<0><<<gQKV, 256, IG_SMEM>>>(                             // 4 on l=0
            x1, x2, sx, D,
            wq1 + (size_t)l * 3 * D * D, wq2 + (size_t)l * 3 * D * D,
            swq + (size_t)l * 3 * D, D,
            bqkv + (size_t)l * 3 * D, qkvb, 3 * D, D);
        attn_kernel<<<B * H, 256, ATT_SMEM>>>(qkvb, ao);
        quant_rows<512><<<M_TOT, 128>>>(ao, D, ao1, ao2, sao, nullptr);
        ig_gemm<0><<<gD, 256, IG_SMEM>>>(
            ao1, ao2, sao, D,
            wo1 + (size_t)l * D * D, wo2 + (size_t)l * D * D,
            swo + (size_t)l * D, D,
            bo + (size_t)l * D, tmp, D, D);
        add_ln_kernel<<<M_TOT, 128>>>(x, tmp, ln1_g + (size_t)l * D,
                                      ln1_b + (size_t)l * D, x1, x2, sx);
        ig_gemm<1><<<gFF, 256, IG_SMEM>>>(
            x1, x2, sx, D,
            w11 + (size_t)l * FF * D, w12 + (size_t)l * FF * D,
            sw1 + (size_t)l * FF, D,
            b1 + (size_t)l * FF, hb, FF, D);
        quant_rows<1024><<<M_TOT, 128>>>(hb, FF, h1, h2, sh, nullptr);
        ig_gemm<0><<<gD, 256, IG_SMEM>>>(
            h1, h2, sh, FF,
            w21 + (size_t)l * D * FF, w22 + (size_t)l * D * FF,
            sw2 + (size_t)l * D, FF,
            b2 + (size_t)l * D, tmp, D, FF);
        add_ln_kernel<<<M_TOT, 128>>>(x, tmp, ln2_g + (size_t)l * D,
                                      ln2_b + (size_t)l * D, x1, x2, sx);
    }

    // Combined head GEMM: C[4096, 2048] = x @ [Wm1_f; Wm1_t]^T
    ig_gemm<0><<<gHD, 256, IG_SMEM>>>(
        x1, x2, sx, D, mc1, mc2, smc, D, nullptr, ftb, 2 * FF, D);
    pairwise_kernel<<<B * 8, 256>>>(ftb, ftb + FF, 2 * FF, bm1, Wm2, bm2, out);
}